// round 14
// baseline (speedup 1.0000x reference)
#include <cuda_runtime.h>
#include <cstdint>

#define NN 50000
#define EE 800000
#define ETPB 256
#define NTILES 3125        // EE / 256 exactly
#define EGRID 296
#define NTTILES 196        // ceil(NN / 256)

typedef unsigned long long ull;
typedef unsigned int u32;

// -------- persistent device scratch --------
__device__ u32   g_featPA[NN * 32];
__device__ u32   g_featPB[NN * 32];
__device__ float g_posA[NN * 3];
__device__ float g_posB[NN * 3];
__device__ float g_msg[NN * 64];
__device__ float g_pagg[NN * 3];
__device__ float g_inv[NN];
__device__ int   g_cnt[NN];
__device__ u32   g_wb[5 * 8192];   // edge weights, k-permuted pairs
__device__ u32   g_wnb[5 * 6144];  // node weights, k-permuted pairs

// -------- helpers --------
__device__ __forceinline__ u32 pk2(float lo, float hi) {
    u32 r;
    asm("cvt.rn.bf16x2.f32 %0, %1, %2;" : "=r"(r) : "f"(hi), "f"(lo));
    return r;
}
__device__ __forceinline__ float ex2a(float x) {
    float r;
    asm("ex2.approx.f32 %0, %1;" : "=f"(r) : "f"(x));
    return r;
}
__device__ __forceinline__ float rcpa(float x) {
    float r;
    asm("rcp.approx.f32 %0, %1;" : "=f"(r) : "f"(x));
    return r;
}
// single silu (prep/low-frequency use)
__device__ __forceinline__ float silu_f(float x) {
    float e = ex2a(fminf(x, 12.0f) * 1.442695041f);
    return x * e * rcpa(1.0f + e);
}
// batched: 4 silus with ONE rcp (shared-denominator trick)
__device__ __forceinline__ void silu4(float x0, float x1, float x2, float x3,
                                      float& s0, float& s1, float& s2, float& s3)
{
    const float L2E = 1.442695041f;
    float e0 = ex2a(fminf(x0, 12.0f) * L2E);
    float e1 = ex2a(fminf(x1, 12.0f) * L2E);
    float e2 = ex2a(fminf(x2, 12.0f) * L2E);
    float e3 = ex2a(fminf(x3, 12.0f) * L2E);
    float d0 = 1.0f + e0, d1 = 1.0f + e1, d2 = 1.0f + e2, d3 = 1.0f + e3;
    float p01 = d0 * d1, p23 = d2 * d3;
    float R = rcpa(p01 * p23);
    s0 = x0 * e0 * (R * d1 * p23);
    s1 = x1 * e1 * (R * d0 * p23);
    s2 = x2 * e2 * (R * p01 * d3);
    s3 = x3 * e3 * (R * p01 * d2);
}

#define MMAB(d, a0, a1, a2, a3, b0, b1)                                            \
    asm volatile("mma.sync.aligned.m16n8k16.row.col.f32.bf16.bf16.f32 "            \
                 "{%0,%1,%2,%3}, {%4,%5,%6,%7}, {%8,%9}, {%0,%1,%2,%3};"           \
                 : "+f"((d)[0]), "+f"((d)[1]), "+f"((d)[2]), "+f"((d)[3])          \
                 : "r"(a0), "r"(a1), "r"(a2), "r"(a3), "r"(b0), "r"(b1))

#define REDV2(p, a, b)                                                             \
    asm volatile("red.global.add.v2.f32 [%0], {%1, %2};" :: "l"(p), "f"(a), "f"(b) : "memory")

#define SHF(v, src) __shfl_sync(0xffffffffu, (v), (src))

// one k16 step: 16 MMAs; B fragments = LDS.64 (k-permuted weights), A scalar (natural)
__device__ __forceinline__ void stepK(float acc[2][8][4], const u32* A, const u32* B,
                                      int Astride, int Bstride, int kwA, int kwB,
                                      int tb, int g, int cc)
{
    u32 b0[8], b1[8];
#pragma unroll
    for (int nt = 0; nt < 8; ++nt) {
        uint2 bv = *(const uint2*)(B + (nt * 8 + g) * Bstride + kwB + 2 * cc);
        b0[nt] = bv.x;
        b1[nt] = bv.y;
    }
#pragma unroll
    for (int mt = 0; mt < 2; ++mt) {
        const u32* ar = A + (tb + mt * 16 + g) * Astride + kwA;
        u32 a0 = ar[cc];
        u32 a1 = ar[8 * Astride + cc];
        u32 a2 = ar[4 + cc];
        u32 a3 = ar[8 * Astride + 4 + cc];
#pragma unroll
        for (int nt = 0; nt < 8; ++nt)
            MMAB(acc[mt][nt], a0, a1, a2, a3, b0[nt], b1[nt]);
    }
}

// -------- edge kernel SMEM layout (permuted-weight strides 72/40) --------
#define O_W1   0        // 64 x 72w = 18432
#define O_W2   18432    // 64 x 40w = 10240
#define O_P1   28672    // 64 x 40w = 10240
#define O_AR   38912    // 256 x 36w = 36864
#define O_AC   75776    // 256 x 36w = 36864
#define O_SXT  112640   // 1024
#define O_SB2  113664   // 256
#define O_SXP  113920   // 512
#define SM_TOT 114432

template <bool DO_MSG, bool DO_POS>
__global__ void __launch_bounds__(ETPB, 2)
edge_kernel(int featSel, int posSel, int layer,
            const float2* __restrict__ ea_g,
            const int* __restrict__ row, const int* __restrict__ col,
            const float* __restrict__ mW1, const float* __restrict__ mb1,
            const float* __restrict__ mb2, const float* __restrict__ pb1,
            const float* __restrict__ pW2, const float* __restrict__ pb2)
{
    extern __shared__ __align__(16) char sm[];
    u32*    W1s  = (u32*)(sm + O_W1);
    u32*    W2s  = (u32*)(sm + O_W2);
    u32*    P1s  = (u32*)(sm + O_P1);
    u32*    A_R  = (u32*)(sm + O_AR);
    u32*    A_C  = (u32*)(sm + O_AC);
    float4* sxT  = (float4*)(sm + O_SXT);
    float*  sxB2 = (float*)(sm + O_SB2);
    float2* sxP  = (float2*)(sm + O_SXP);

    const int tid = threadIdx.x;

    {
        const u32* wsrc = g_wb + layer * 8192;
        for (int i = tid; i < 4096; i += ETPB) {
            int n = i >> 6, w = i & 63;
            W1s[n * 72 + w] = wsrc[i];
        }
        for (int i = tid; i < 2048; i += ETPB) {
            int n = i >> 5, w = i & 31;
            W2s[n * 40 + w] = wsrc[4096 + i];
            P1s[n * 40 + w] = wsrc[6144 + i];
        }
    }
    if (tid < 64) {
        sxT[tid] = make_float4(mW1[128 * 64 + tid], mW1[129 * 64 + tid], mW1[130 * 64 + tid], mb1[tid]);
        sxB2[tid] = mb2[tid];
        sxP[tid] = make_float2(pb1[tid], pW2[tid]);
    }
    const float pb2v = pb2[0];
    __syncthreads();

    const u32* featP = featSel ? g_featPB : g_featPA;
    const float* posIn = posSel ? g_posB : g_posA;

    const int lane = tid & 31;
    const int g  = lane >> 2;
    const int cc = lane & 3;
    const int tb = (tid >> 5) * 32;
    const int sub   = lane >> 3;
    const int chunk = lane & 7;

    for (int tile = blockIdx.x; tile < NTILES; tile += gridDim.x) {
        __syncwarp();
        const int e = tile * ETPB + tid;
        const int r = row[e], c = col[e];
        const float dx = posIn[r * 3 + 0] - posIn[c * 3 + 0];
        const float dy = posIn[r * 3 + 1] - posIn[c * 3 + 1];
        const float dz = posIn[r * 3 + 2] - posIn[c * 3 + 2];
        const float dist = dx * dx + dy * dy + dz * dz;
        const float2 ea = ea_g[e];

        // warp-cooperative gather: 8 lanes load one full 128B feat row
#pragma unroll
        for (int p = 0; p < 8; ++p) {
            const int q = p * 4 + sub;
            const int rq = SHF(r, q);
            const int cq = SHF(c, q);
            *(uint4*)(A_R + (tb + q) * 36 + chunk * 4) =
                *(const uint4*)(featP + (size_t)rq * 32 + chunk * 4);
            *(uint4*)(A_C + (tb + q) * 36 + chunk * 4) =
                *(const uint4*)(featP + (size_t)cq * 32 + chunk * 4);
        }
        __syncwarp();

        float acc[2][8][4];
#pragma unroll
        for (int mt = 0; mt < 2; ++mt)
#pragma unroll
            for (int nt = 0; nt < 8; ++nt)
#pragma unroll
                for (int i = 0; i < 4; ++i) acc[mt][nt][i] = 0.0f;

        // ---- stage 1 ----
#pragma unroll
        for (int kt = 0; kt < 4; ++kt) stepK(acc, A_R, W1s, 36, 72, kt * 8, kt * 8, tb, g, cc);
#pragma unroll
        for (int kt = 0; kt < 4; ++kt) stepK(acc, A_C, W1s, 36, 72, kt * 8, 32 + kt * 8, tb, g, cc);

        // ---- epilogue 1 ----
#pragma unroll
        for (int mt = 0; mt < 2; ++mt) {
            const int q0 = mt * 16 + g, q1 = q0 + 8;
            const float ex0 = SHF(ea.x, q0), ey0 = SHF(ea.y, q0), ds0 = SHF(dist, q0);
            const float ex1 = SHF(ea.x, q1), ey1 = SHF(ea.y, q1), ds1 = SHF(dist, q1);
            const int e0 = tb + q0, e1 = tb + q1;
#pragma unroll
            for (int nt = 0; nt < 8; ++nt) {
                const int n0 = nt * 8 + 2 * cc;
                const float4 t0 = sxT[n0], t1 = sxT[n0 + 1];
                float v00 = acc[mt][nt][0] + t0.w + ex0 * t0.x + ey0 * t0.y + ds0 * t0.z;
                float v01 = acc[mt][nt][1] + t1.w + ex0 * t1.x + ey0 * t1.y + ds0 * t1.z;
                float v10 = acc[mt][nt][2] + t0.w + ex1 * t0.x + ey1 * t0.y + ds1 * t0.z;
                float v11 = acc[mt][nt][3] + t1.w + ex1 * t1.x + ey1 * t1.y + ds1 * t1.z;
                float s00, s01, s10, s11;
                silu4(v00, v01, v10, v11, s00, s01, s10, s11);
                const int word = nt * 4 + cc;
                A_R[e0 * 36 + word] = pk2(s00, s01);
                A_R[e1 * 36 + word] = pk2(s10, s11);
            }
        }
        __syncwarp();

        // ---- stage 2 ----
#pragma unroll
        for (int mt = 0; mt < 2; ++mt)
#pragma unroll
            for (int nt = 0; nt < 8; ++nt)
#pragma unroll
                for (int i = 0; i < 4; ++i) acc[mt][nt][i] = 0.0f;
#pragma unroll
        for (int kt = 0; kt < 4; ++kt) stepK(acc, A_R, W2s, 36, 40, kt * 8, kt * 8, tb, g, cc);

        // ---- epilogue 2 ----
        int r0s[2], r1s[2];
#pragma unroll
        for (int mt = 0; mt < 2; ++mt) {
            const int q0 = mt * 16 + g, q1 = q0 + 8;
            const int r0 = SHF(r, q0), r1 = SHF(r, q1);
            r0s[mt] = r0; r1s[mt] = r1;
            const int e0 = tb + q0, e1 = tb + q1;
#pragma unroll
            for (int nt = 0; nt < 8; ++nt) {
                const int n0 = nt * 8 + 2 * cc;
                float m00, m01, m10, m11;
                silu4(acc[mt][nt][0] + sxB2[n0], acc[mt][nt][1] + sxB2[n0 + 1],
                      acc[mt][nt][2] + sxB2[n0], acc[mt][nt][3] + sxB2[n0 + 1],
                      m00, m01, m10, m11);
                if (DO_MSG) {
                    REDV2(g_msg + (size_t)r0 * 64 + n0, m00, m01);
                    REDV2(g_msg + (size_t)r1 * 64 + n0, m10, m11);
                }
                if (DO_POS) {
                    const int word = nt * 4 + cc;
                    A_C[e0 * 36 + word] = pk2(m00, m01);
                    A_C[e1 * 36 + word] = pk2(m10, m11);
                }
            }
        }

        if (DO_POS) {
            __syncwarp();
            // ---- stage 3 ----
#pragma unroll
            for (int mt = 0; mt < 2; ++mt)
#pragma unroll
                for (int nt = 0; nt < 8; ++nt)
#pragma unroll
                    for (int i = 0; i < 4; ++i) acc[mt][nt][i] = 0.0f;
#pragma unroll
            for (int kt = 0; kt < 4; ++kt) stepK(acc, A_C, P1s, 36, 40, kt * 8, kt * 8, tb, g, cc);

            // ---- epilogue 3 ----
#pragma unroll
            for (int mt = 0; mt < 2; ++mt) {
                const int q0 = mt * 16 + g, q1 = q0 + 8;
                float w0 = 0.0f, w1 = 0.0f;
#pragma unroll
                for (int nt = 0; nt < 8; ++nt) {
                    const int n0 = nt * 8 + 2 * cc;
                    const float2 p0 = sxP[n0], p1 = sxP[n0 + 1];
                    float s00, s01, s10, s11;
                    silu4(acc[mt][nt][0] + p0.x, acc[mt][nt][1] + p1.x,
                          acc[mt][nt][2] + p0.x, acc[mt][nt][3] + p1.x,
                          s00, s01, s10, s11);
                    w0 += s00 * p0.y + s01 * p1.y;
                    w1 += s10 * p0.y + s11 * p1.y;
                }
                w0 += __shfl_xor_sync(0xffffffffu, w0, 1);
                w0 += __shfl_xor_sync(0xffffffffu, w0, 2);
                w1 += __shfl_xor_sync(0xffffffffu, w1, 1);
                w1 += __shfl_xor_sync(0xffffffffu, w1, 2);
                const float dx0 = SHF(dx, q0), dy0 = SHF(dy, q0), dz0 = SHF(dz, q0);
                const float dx1 = SHF(dx, q1), dy1 = SHF(dy, q1), dz1 = SHF(dz, q1);
                if (cc == 0) {
                    const int r0 = r0s[mt], r1 = r1s[mt];
                    const float wa = w0 + pb2v, wb = w1 + pb2v;
                    atomicAdd(&g_pagg[r0 * 3 + 0], dx0 * wa);
                    atomicAdd(&g_pagg[r0 * 3 + 1], dy0 * wa);
                    atomicAdd(&g_pagg[r0 * 3 + 2], dz0 * wa);
                    atomicAdd(&g_pagg[r1 * 3 + 0], dx1 * wb);
                    atomicAdd(&g_pagg[r1 * 3 + 1], dy1 * wb);
                    atomicAdd(&g_pagg[r1 * 3 + 2], dz1 * wb);
                }
            }
        }
    }
}

// -------- node MMA kernel (permuted weights, silu4) --------
#define NO_W1  0        // 64 x 72w = 18432
#define NO_W2  18432    // 64 x 40w = 10240
#define NO_AF  28672    // 36864
#define NO_AM  65536    // 36864
#define NO_B1  102400   // 256
#define NO_B2  102656   // 256
#define NSM_TOT 102912

template <bool DO_POS>
__global__ void __launch_bounds__(ETPB, 2)
node_mma_kernel(int featSel, int posSel, int layer,
                const float* __restrict__ nb1, const float* __restrict__ nb2)
{
    extern __shared__ __align__(16) char sm[];
    u32*   N1s = (u32*)(sm + NO_W1);
    u32*   N2s = (u32*)(sm + NO_W2);
    u32*   A_F = (u32*)(sm + NO_AF);
    u32*   A_M = (u32*)(sm + NO_AM);
    float* b1s = (float*)(sm + NO_B1);
    float* b2s = (float*)(sm + NO_B2);

    const int tid = threadIdx.x;

    {
        const u32* wsrc = g_wnb + layer * 6144;
        for (int i = tid; i < 4096; i += ETPB) {
            int n = i >> 6, w = i & 63;
            N1s[n * 72 + w] = wsrc[i];
        }
        for (int i = tid; i < 2048; i += ETPB) {
            int n = i >> 5, w = i & 31;
            N2s[n * 40 + w] = wsrc[4096 + i];
        }
    }
    if (tid < 64) { b1s[tid] = nb1[tid]; b2s[tid] = nb2[tid]; }
    __syncthreads();

    const u32* fin  = featSel ? g_featPB : g_featPA;
    u32*       fout = featSel ? g_featPA : g_featPB;
    const float* posIn  = posSel ? g_posB : g_posA;
    float*       posOut = posSel ? g_posA : g_posB;

    const int lane = tid & 31;
    const int g  = lane >> 2;
    const int cc = lane & 3;
    const int tb = (tid >> 5) * 32;

    const int tile = blockIdx.x;
    const int n = tile * ETPB + tid;
    const bool valid = (n < NN);
    const int nc = valid ? n : (NN - 1);
    const float inv = g_inv[nc];

    {
        const uint4* fr4 = (const uint4*)(fin + (size_t)nc * 32);
        u32* aF = A_F + tid * 36;
#pragma unroll
        for (int q = 0; q < 8; ++q) *(uint4*)(aF + 4 * q) = fr4[q];

        const float4* fm = (const float4*)(g_msg + (size_t)nc * 64);
        u32* aM = A_M + tid * 36;
#pragma unroll
        for (int q = 0; q < 16; ++q) {
            float4 v = fm[q];
            aM[2 * q]     = pk2(v.x * inv, v.y * inv);
            aM[2 * q + 1] = pk2(v.z * inv, v.w * inv);
        }
    }
    if (valid) {
        float4* fm = (float4*)(g_msg + (size_t)n * 64);
        const float4 z4 = make_float4(0.f, 0.f, 0.f, 0.f);
#pragma unroll
        for (int q = 0; q < 16; ++q) fm[q] = z4;
        if (DO_POS) {
            posOut[n * 3 + 0] = posIn[n * 3 + 0] + g_pagg[n * 3 + 0] * inv;
            posOut[n * 3 + 1] = posIn[n * 3 + 1] + g_pagg[n * 3 + 1] * inv;
            posOut[n * 3 + 2] = posIn[n * 3 + 2] + g_pagg[n * 3 + 2] * inv;
            g_pagg[n * 3 + 0] = 0.f;
            g_pagg[n * 3 + 1] = 0.f;
            g_pagg[n * 3 + 2] = 0.f;
        }
    }
    __syncwarp();

    float acc[2][8][4];
#pragma unroll
    for (int mt = 0; mt < 2; ++mt)
#pragma unroll
        for (int nt = 0; nt < 8; ++nt)
#pragma unroll
            for (int i = 0; i < 4; ++i) acc[mt][nt][i] = 0.0f;

#pragma unroll
    for (int kt = 0; kt < 4; ++kt) stepK(acc, A_F, N1s, 36, 72, kt * 8, kt * 8, tb, g, cc);
#pragma unroll
    for (int kt = 0; kt < 4; ++kt) stepK(acc, A_M, N1s, 36, 72, kt * 8, 32 + kt * 8, tb, g, cc);

#pragma unroll
    for (int mt = 0; mt < 2; ++mt) {
        const int e0 = tb + mt * 16 + g, e1 = e0 + 8;
#pragma unroll
        for (int nt = 0; nt < 8; ++nt) {
            const int n0 = nt * 8 + 2 * cc;
            float s00, s01, s10, s11;
            silu4(acc[mt][nt][0] + b1s[n0], acc[mt][nt][1] + b1s[n0 + 1],
                  acc[mt][nt][2] + b1s[n0], acc[mt][nt][3] + b1s[n0 + 1],
                  s00, s01, s10, s11);
            const int word = nt * 4 + cc;
            A_F[e0 * 36 + word] = pk2(s00, s01);
            A_F[e1 * 36 + word] = pk2(s10, s11);
        }
    }
    __syncwarp();

#pragma unroll
    for (int mt = 0; mt < 2; ++mt)
#pragma unroll
        for (int nt = 0; nt < 8; ++nt)
#pragma unroll
            for (int i = 0; i < 4; ++i) acc[mt][nt][i] = 0.0f;
#pragma unroll
    for (int kt = 0; kt < 4; ++kt) stepK(acc, A_F, N2s, 36, 40, kt * 8, kt * 8, tb, g, cc);

#pragma unroll
    for (int mt = 0; mt < 2; ++mt) {
        const int m0 = tile * ETPB + tb + mt * 16 + g;
        const int m1 = m0 + 8;
#pragma unroll
        for (int nt = 0; nt < 8; ++nt) {
            const int n0 = nt * 8 + 2 * cc;
            const int word = nt * 4 + cc;
            if (m0 < NN)
                fout[(size_t)m0 * 32 + word] = pk2(acc[mt][nt][0] + b2s[n0], acc[mt][nt][1] + b2s[n0 + 1]);
            if (m1 < NN)
                fout[(size_t)m1 * 32 + word] = pk2(acc[mt][nt][2] + b2s[n0], acc[mt][nt][3] + b2s[n0 + 1]);
        }
    }
}

// ================= helper kernels =================
__global__ void init_kernel(const float* __restrict__ pos) {
    int i = blockIdx.x * blockDim.x + threadIdx.x;
    if (i < NN * 64) g_msg[i] = 0.0f;
    if (i < NN * 3) { g_pagg[i] = 0.0f; g_posB[i] = pos[i]; }
    if (i < NN) g_cnt[i] = 0;
}
__global__ void count_kernel(const int* __restrict__ row) {
    int e = blockIdx.x * blockDim.x + threadIdx.x;
    if (e < EE) atomicAdd(&g_cnt[row[e]], 1);
}
// k-permuted weight position: p = P&7; k = 16*(P>>3) + (p odd ? p+7 : p)
__global__ void prep_kernel(const float* __restrict__ nf, const float* __restrict__ embW,
                            const float* __restrict__ embb,
                            const float* __restrict__ mW1, const float* __restrict__ mW2,
                            const float* __restrict__ pW1,
                            const float* __restrict__ nW1, const float* __restrict__ nW2) {
    int i = blockIdx.x * blockDim.x + threadIdx.x;
    if (i < NN) g_inv[i] = 1.0f / fmaxf((float)g_cnt[i], 1.0f);
    if (i < NN * 32) {
        int n = i >> 5, w = i & 31;
        int J = 2 * w;
        float v0 = nf[2 * n] * embW[J] + nf[2 * n + 1] * embW[64 + J] + embb[J];
        float v1 = nf[2 * n] * embW[J + 1] + nf[2 * n + 1] * embW[64 + J + 1] + embb[J + 1];
        g_featPA[i] = pk2(v0, v1);
    }
    if (i < 5 * 8192) {
        int l = i >> 13, rem = i & 8191;
        u32 out;
        if (rem < 4096) {
            int n = rem >> 6, P = rem & 63;
            int p = P & 7;
            int k = 16 * (P >> 3) + ((p & 1) ? p + 7 : p);
            out = pk2(mW1[l * 131 * 64 + k * 64 + n], mW1[l * 131 * 64 + (k + 1) * 64 + n]);
        } else {
            int rem2 = rem - 4096;
            int mat = rem2 >> 11, idx = rem2 & 2047;
            int n = idx >> 5, P = idx & 31;
            int p = P & 7;
            int k = 16 * (P >> 3) + ((p & 1) ? p + 7 : p);
            const float* src = (mat == 0) ? mW2 : pW1;
            out = pk2(src[l * 4096 + k * 64 + n], src[l * 4096 + (k + 1) * 64 + n]);
        }
        g_wb[i] = out;
    }
    if (i < 5 * 6144) {
        int l = i / 6144, rem = i % 6144;
        u32 out;
        if (rem < 4096) {
            int n = rem >> 6, P = rem & 63;
            int p = P & 7;
            int k = 16 * (P >> 3) + ((p & 1) ? p + 7 : p);
            out = pk2(nW1[l * 8192 + k * 64 + n], nW1[l * 8192 + (k + 1) * 64 + n]);
        } else {
            int idx = rem - 4096;
            int n = idx >> 5, P = idx & 31;
            int p = P & 7;
            int k = 16 * (P >> 3) + ((p & 1) ? p + 7 : p);
            out = pk2(nW2[l * 4096 + k * 64 + n], nW2[l * 4096 + (k + 1) * 64 + n]);
        }
        g_wnb[i] = out;
    }
}
__global__ void pos_final_kernel(float* __restrict__ out) {
    int i = blockIdx.x * blockDim.x + threadIdx.x;
    if (i < NN * 3) {
        int n = i / 3;
        out[i] = g_posA[i] + g_pagg[i] * g_inv[n];
    }
}

extern "C" void kernel_launch(void* const* d_in, const int* in_sizes, int n_in,
                              void* d_out, int out_size)
{
    const float*  node_feat = (const float*)d_in[0];
    const float*  node_pos  = (const float*)d_in[1];
    const float2* edge_attr = (const float2*)d_in[2];
    const int*    row       = (const int*)d_in[3];
    const int*    col       = (const int*)d_in[4];
    const float*  emb_W     = (const float*)d_in[5];
    const float*  emb_b     = (const float*)d_in[6];
    const float*  mW1 = (const float*)d_in[7];
    const float*  mb1 = (const float*)d_in[8];
    const float*  mW2 = (const float*)d_in[9];
    const float*  mb2 = (const float*)d_in[10];
    const float*  pW1 = (const float*)d_in[11];
    const float*  pb1 = (const float*)d_in[12];
    const float*  pW2 = (const float*)d_in[13];
    const float*  pb2 = (const float*)d_in[14];
    const float*  nW1 = (const float*)d_in[15];
    const float*  nb1 = (const float*)d_in[16];
    const float*  nW2 = (const float*)d_in[17];
    const float*  nb2 = (const float*)d_in[18];
    float* out = (float*)d_out;

    cudaFuncSetAttribute(edge_kernel<true, false>, cudaFuncAttributeMaxDynamicSharedMemorySize, SM_TOT);
    cudaFuncSetAttribute(edge_kernel<true, true>,  cudaFuncAttributeMaxDynamicSharedMemorySize, SM_TOT);
    cudaFuncSetAttribute(edge_kernel<false, true>, cudaFuncAttributeMaxDynamicSharedMemorySize, SM_TOT);
    cudaFuncSetAttribute(node_mma_kernel<false>, cudaFuncAttributeMaxDynamicSharedMemorySize, NSM_TOT);
    cudaFuncSetAttribute(node_mma_kernel<true>,  cudaFuncAttributeMaxDynamicSharedMemorySize, NSM_TOT);

    const int ZG = (NN * 64 + 255) / 256;

    init_kernel<<<ZG, 256>>>(node_pos);
    count_kernel<<<(EE + 255) / 256, 256>>>(row);
    prep_kernel<<<ZG, 256>>>(node_feat, emb_W, emb_b, mW1, mW2, pW1, nW1, nW2);

#define EDGE_ARGS(l) edge_attr, row, col, \
        mW1 + (l) * 131 * 64, mb1 + (l) * 64, mb2 + (l) * 64, \
        pb1 + (l) * 64, pW2 + (l) * 64, pb2 + (l)

    // L0 (com_node_feat_net): feat only
    edge_kernel<true, false><<<EGRID, ETPB, SM_TOT>>>(0, 1, 0, EDGE_ARGS(0));
    node_mma_kernel<false><<<NTTILES, ETPB, NSM_TOT>>>(0, 1, 0, nb1 + 0, nb2 + 0);
    // L1
    edge_kernel<true, true><<<EGRID, ETPB, SM_TOT>>>(1, 1, 1, EDGE_ARGS(1));
    node_mma_kernel<true><<<NTTILES, ETPB, NSM_TOT>>>(1, 1, 1, nb1 + 64, nb2 + 64);
    // L2
    edge_kernel<true, true><<<EGRID, ETPB, SM_TOT>>>(0, 0, 2, EDGE_ARGS(2));
    node_mma_kernel<true><<<NTTILES, ETPB, NSM_TOT>>>(0, 0, 2, nb1 + 128, nb2 + 128);
    // L3
    edge_kernel<true, true><<<EGRID, ETPB, SM_TOT>>>(1, 1, 3, EDGE_ARGS(3));
    node_mma_kernel<true><<<NTTILES, ETPB, NSM_TOT>>>(1, 1, 3, nb1 + 192, nb2 + 192);
    // L4: pos only
    edge_kernel<false, true><<<EGRID, ETPB, SM_TOT>>>(0, 0, 4, EDGE_ARGS(4));
    pos_final_kernel<<<(NN * 3 + 255) / 256, 256>>>(out);

#undef EDGE_ARGS
}

// round 15
// speedup vs baseline: 1.2859x; 1.2859x over previous
#include <cuda_runtime.h>
#include <cstdint>

#define NN 50000
#define EE 800000
#define ETPB 256
#define NTILES 3125        // EE / 256 exactly
#define EGRID 296
#define NTTILES 196        // ceil(NN / 256)

typedef unsigned long long ull;
typedef unsigned int u32;

// -------- persistent device scratch --------
__device__ u32   g_featPA[NN * 32];
__device__ u32   g_featPB[NN * 32];
__device__ float g_posA[NN * 3];
__device__ float g_posB[NN * 3];
__device__ float g_msg[NN * 64];
__device__ float g_pagg[NN * 3];
__device__ float g_inv[NN];
__device__ int   g_cnt[NN];
__device__ u32   g_wb[5 * 8192];   // edge weights: W1t 64n x 64w, W2t 64n x 32w, P1t 64n x 32w (natural k-pair order)
__device__ u32   g_wnb[5 * 6144];  // node weights: nW1t 64n x 64w, nW2t 64n x 32w

// -------- helpers --------
// silu via tanh: silu(x) = hx + hx*tanh(hx), hx = x/2.  1 MUFU + 1 MUL + 1 FMA.
__device__ __forceinline__ float silu_f(float x) {
    float hx = 0.5f * x;
    float t;
    asm("tanh.approx.f32 %0, %1;" : "=f"(t) : "f"(hx));
    return hx + hx * t;
}
__device__ __forceinline__ u32 pk2(float lo, float hi) {
    u32 r;
    asm("cvt.rn.bf16x2.f32 %0, %1, %2;" : "=r"(r) : "f"(hi), "f"(lo));
    return r;
}

#define MMAB(d, a0, a1, a2, a3, b0, b1)                                            \
    asm volatile("mma.sync.aligned.m16n8k16.row.col.f32.bf16.bf16.f32 "            \
                 "{%0,%1,%2,%3}, {%4,%5,%6,%7}, {%8,%9}, {%0,%1,%2,%3};"           \
                 : "+f"((d)[0]), "+f"((d)[1]), "+f"((d)[2]), "+f"((d)[3])          \
                 : "r"(a0), "r"(a1), "r"(a2), "r"(a3), "r"(b0), "r"(b1))

#define REDV2(p, a, b)                                                             \
    asm volatile("red.global.add.v2.f32 [%0], {%1, %2};" :: "l"(p), "f"(a), "f"(b) : "memory")

#define SHF(v, src) __shfl_sync(0xffffffffu, (v), (src))

// one k16 step: 16 MMAs; all fragments are single 32-bit shared words (natural k-pair order)
__device__ __forceinline__ void stepK(float acc[2][8][4], const u32* A, const u32* B,
                                      int Astride, int Bstride, int kwA, int kwB,
                                      int tb, int g, int cc)
{
    u32 b0[8], b1[8];
#pragma unroll
    for (int nt = 0; nt < 8; ++nt) {
        const u32* br = B + (nt * 8 + g) * Bstride + kwB;
        b0[nt] = br[cc];
        b1[nt] = br[4 + cc];
    }
#pragma unroll
    for (int mt = 0; mt < 2; ++mt) {
        const u32* ar = A + (tb + mt * 16 + g) * Astride + kwA;
        u32 a0 = ar[cc];
        u32 a1 = ar[8 * Astride + cc];
        u32 a2 = ar[4 + cc];
        u32 a3 = ar[8 * Astride + 4 + cc];
#pragma unroll
        for (int nt = 0; nt < 8; ++nt)
            MMAB(acc[mt][nt], a0, a1, a2, a3, b0[nt], b1[nt]);
    }
}

// -------- edge kernel SMEM layout (identical to R12) --------
#define O_W1   0
#define O_W2   17408
#define O_P1   26624
#define O_AR   35840
#define O_AC   72704
#define O_SXT  109568
#define O_SB2  110592
#define O_SXP  110848
#define SM_TOT 111360

template <bool DO_MSG, bool DO_POS>
__global__ void __launch_bounds__(ETPB, 2)
edge_kernel(int featSel, int posSel, int layer,
            const float2* __restrict__ ea_g,
            const int* __restrict__ row, const int* __restrict__ col,
            const float* __restrict__ mW1, const float* __restrict__ mb1,
            const float* __restrict__ mb2, const float* __restrict__ pb1,
            const float* __restrict__ pW2, const float* __restrict__ pb2)
{
    extern __shared__ __align__(16) char sm[];
    u32*    W1s  = (u32*)(sm + O_W1);
    u32*    W2s  = (u32*)(sm + O_W2);
    u32*    P1s  = (u32*)(sm + O_P1);
    u32*    A_R  = (u32*)(sm + O_AR);
    u32*    A_C  = (u32*)(sm + O_AC);
    float4* sxT  = (float4*)(sm + O_SXT);
    float*  sxB2 = (float*)(sm + O_SB2);
    float2* sxP  = (float2*)(sm + O_SXP);

    const int tid = threadIdx.x;

    {
        const u32* wsrc = g_wb + layer * 8192;
        for (int i = tid; i < 4096; i += ETPB) {
            int n = i >> 6, w = i & 63;
            W1s[n * 68 + w] = wsrc[i];
        }
        for (int i = tid; i < 2048; i += ETPB) {
            int n = i >> 5, w = i & 31;
            W2s[n * 36 + w] = wsrc[4096 + i];
            P1s[n * 36 + w] = wsrc[6144 + i];
        }
    }
    if (tid < 64) {
        sxT[tid] = make_float4(mW1[128 * 64 + tid], mW1[129 * 64 + tid], mW1[130 * 64 + tid], mb1[tid]);
        sxB2[tid] = mb2[tid];
        sxP[tid] = make_float2(pb1[tid], pW2[tid]);
    }
    const float pb2v = pb2[0];
    __syncthreads();

    const u32* featP = featSel ? g_featPB : g_featPA;
    const float* posIn = posSel ? g_posB : g_posA;

    const int lane = tid & 31;
    const int g  = lane >> 2;
    const int cc = lane & 3;
    const int tb = (tid >> 5) * 32;
    const int sub   = lane >> 3;   // gather: which row of the 4-row pass
    const int chunk = lane & 7;    // gather: 16B chunk within the 128B row

    for (int tile = blockIdx.x; tile < NTILES; tile += gridDim.x) {
        __syncwarp();
        const int e = tile * ETPB + tid;
        const int r = row[e], c = col[e];
        const float dx = posIn[r * 3 + 0] - posIn[c * 3 + 0];
        const float dy = posIn[r * 3 + 1] - posIn[c * 3 + 1];
        const float dz = posIn[r * 3 + 2] - posIn[c * 3 + 2];
        const float dist = dx * dx + dy * dy + dz * dz;
        const float2 ea = ea_g[e];

        // warp-cooperative gather: 8 lanes load one full 128B feat row
#pragma unroll
        for (int p = 0; p < 8; ++p) {
            const int q = p * 4 + sub;
            const int rq = SHF(r, q);
            const int cq = SHF(c, q);
            *(uint4*)(A_R + (tb + q) * 36 + chunk * 4) =
                *(const uint4*)(featP + (size_t)rq * 32 + chunk * 4);
            *(uint4*)(A_C + (tb + q) * 36 + chunk * 4) =
                *(const uint4*)(featP + (size_t)cq * 32 + chunk * 4);
        }
        __syncwarp();

        float acc[2][8][4];
#pragma unroll
        for (int mt = 0; mt < 2; ++mt)
#pragma unroll
            for (int nt = 0; nt < 8; ++nt)
#pragma unroll
                for (int i = 0; i < 4; ++i) acc[mt][nt][i] = 0.0f;

        // ---- stage 1 ----
#pragma unroll
        for (int kt = 0; kt < 4; ++kt) stepK(acc, A_R, W1s, 36, 68, kt * 8, kt * 8, tb, g, cc);
#pragma unroll
        for (int kt = 0; kt < 4; ++kt) stepK(acc, A_C, W1s, 36, 68, kt * 8, 32 + kt * 8, tb, g, cc);

        // ---- epilogue 1 ----
#pragma unroll
        for (int mt = 0; mt < 2; ++mt) {
            const int q0 = mt * 16 + g, q1 = q0 + 8;
            const float ex0 = SHF(ea.x, q0), ey0 = SHF(ea.y, q0), ds0 = SHF(dist, q0);
            const float ex1 = SHF(ea.x, q1), ey1 = SHF(ea.y, q1), ds1 = SHF(dist, q1);
            const int e0 = tb + q0, e1 = tb + q1;
#pragma unroll
            for (int nt = 0; nt < 8; ++nt) {
                const int n0 = nt * 8 + 2 * cc;
                const float4 t0 = sxT[n0], t1 = sxT[n0 + 1];
                float v00 = silu_f(acc[mt][nt][0] + t0.w + ex0 * t0.x + ey0 * t0.y + ds0 * t0.z);
                float v01 = silu_f(acc[mt][nt][1] + t1.w + ex0 * t1.x + ey0 * t1.y + ds0 * t1.z);
                float v10 = silu_f(acc[mt][nt][2] + t0.w + ex1 * t0.x + ey1 * t0.y + ds1 * t0.z);
                float v11 = silu_f(acc[mt][nt][3] + t1.w + ex1 * t1.x + ey1 * t1.y + ds1 * t1.z);
                const int word = nt * 4 + cc;
                A_R[e0 * 36 + word] = pk2(v00, v01);
                A_R[e1 * 36 + word] = pk2(v10, v11);
            }
        }
        __syncwarp();

        // ---- stage 2 ----
#pragma unroll
        for (int mt = 0; mt < 2; ++mt)
#pragma unroll
            for (int nt = 0; nt < 8; ++nt)
#pragma unroll
                for (int i = 0; i < 4; ++i) acc[mt][nt][i] = 0.0f;
#pragma unroll
        for (int kt = 0; kt < 4; ++kt) stepK(acc, A_R, W2s, 36, 36, kt * 8, kt * 8, tb, g, cc);

        // ---- epilogue 2 ----
        int r0s[2], r1s[2];
#pragma unroll
        for (int mt = 0; mt < 2; ++mt) {
            const int q0 = mt * 16 + g, q1 = q0 + 8;
            const int r0 = SHF(r, q0), r1 = SHF(r, q1);
            r0s[mt] = r0; r1s[mt] = r1;
            const int e0 = tb + q0, e1 = tb + q1;
#pragma unroll
            for (int nt = 0; nt < 8; ++nt) {
                const int n0 = nt * 8 + 2 * cc;
                float m00 = silu_f(acc[mt][nt][0] + sxB2[n0]);
                float m01 = silu_f(acc[mt][nt][1] + sxB2[n0 + 1]);
                float m10 = silu_f(acc[mt][nt][2] + sxB2[n0]);
                float m11 = silu_f(acc[mt][nt][3] + sxB2[n0 + 1]);
                if (DO_MSG) {
                    REDV2(g_msg + (size_t)r0 * 64 + n0, m00, m01);
                    REDV2(g_msg + (size_t)r1 * 64 + n0, m10, m11);
                }
                if (DO_POS) {
                    const int word = nt * 4 + cc;
                    A_C[e0 * 36 + word] = pk2(m00, m01);
                    A_C[e1 * 36 + word] = pk2(m10, m11);
                }
            }
        }

        if (DO_POS) {
            __syncwarp();
            // ---- stage 3 ----
#pragma unroll
            for (int mt = 0; mt < 2; ++mt)
#pragma unroll
                for (int nt = 0; nt < 8; ++nt)
#pragma unroll
                    for (int i = 0; i < 4; ++i) acc[mt][nt][i] = 0.0f;
#pragma unroll
            for (int kt = 0; kt < 4; ++kt) stepK(acc, A_C, P1s, 36, 36, kt * 8, kt * 8, tb, g, cc);

            // ---- epilogue 3 ----
#pragma unroll
            for (int mt = 0; mt < 2; ++mt) {
                const int q0 = mt * 16 + g, q1 = q0 + 8;
                float w0 = 0.0f, w1 = 0.0f;
#pragma unroll
                for (int nt = 0; nt < 8; ++nt) {
                    const int n0 = nt * 8 + 2 * cc;
                    const float2 p0 = sxP[n0], p1 = sxP[n0 + 1];
                    w0 += silu_f(acc[mt][nt][0] + p0.x) * p0.y + silu_f(acc[mt][nt][1] + p1.x) * p1.y;
                    w1 += silu_f(acc[mt][nt][2] + p0.x) * p0.y + silu_f(acc[mt][nt][3] + p1.x) * p1.y;
                }
                w0 += __shfl_xor_sync(0xffffffffu, w0, 1);
                w0 += __shfl_xor_sync(0xffffffffu, w0, 2);
                w1 += __shfl_xor_sync(0xffffffffu, w1, 1);
                w1 += __shfl_xor_sync(0xffffffffu, w1, 2);
                const float dx0 = SHF(dx, q0), dy0 = SHF(dy, q0), dz0 = SHF(dz, q0);
                const float dx1 = SHF(dx, q1), dy1 = SHF(dy, q1), dz1 = SHF(dz, q1);
                if (cc == 0) {
                    const int r0 = r0s[mt], r1 = r1s[mt];
                    const float wa = w0 + pb2v, wb = w1 + pb2v;
                    atomicAdd(&g_pagg[r0 * 3 + 0], dx0 * wa);
                    atomicAdd(&g_pagg[r0 * 3 + 1], dy0 * wa);
                    atomicAdd(&g_pagg[r0 * 3 + 2], dz0 * wa);
                    atomicAdd(&g_pagg[r1 * 3 + 0], dx1 * wb);
                    atomicAdd(&g_pagg[r1 * 3 + 1], dy1 * wb);
                    atomicAdd(&g_pagg[r1 * 3 + 2], dz1 * wb);
                }
            }
        }
    }
}

// -------- node MMA kernel (identical to R12 + tanh silu) --------
#define NO_W1  0
#define NO_W2  17408
#define NO_AF  26624
#define NO_AM  63488
#define NO_B1  100352
#define NO_B2  100608
#define NSM_TOT 100864

template <bool DO_POS>
__global__ void __launch_bounds__(ETPB, 2)
node_mma_kernel(int featSel, int posSel, int layer,
                const float* __restrict__ nb1, const float* __restrict__ nb2)
{
    extern __shared__ __align__(16) char sm[];
    u32*   N1s = (u32*)(sm + NO_W1);
    u32*   N2s = (u32*)(sm + NO_W2);
    u32*   A_F = (u32*)(sm + NO_AF);
    u32*   A_M = (u32*)(sm + NO_AM);
    float* b1s = (float*)(sm + NO_B1);
    float* b2s = (float*)(sm + NO_B2);

    const int tid = threadIdx.x;

    {
        const u32* wsrc = g_wnb + layer * 6144;
        for (int i = tid; i < 4096; i += ETPB) {
            int n = i >> 6, w = i & 63;
            N1s[n * 68 + w] = wsrc[i];
        }
        for (int i = tid; i < 2048; i += ETPB) {
            int n = i >> 5, w = i & 31;
            N2s[n * 36 + w] = wsrc[4096 + i];
        }
    }
    if (tid < 64) { b1s[tid] = nb1[tid]; b2s[tid] = nb2[tid]; }
    __syncthreads();

    const u32* fin  = featSel ? g_featPB : g_featPA;
    u32*       fout = featSel ? g_featPA : g_featPB;
    const float* posIn  = posSel ? g_posB : g_posA;
    float*       posOut = posSel ? g_posA : g_posB;

    const int lane = tid & 31;
    const int g  = lane >> 2;
    const int cc = lane & 3;
    const int tb = (tid >> 5) * 32;

    const int tile = blockIdx.x;
    const int n = tile * ETPB + tid;
    const bool valid = (n < NN);
    const int nc = valid ? n : (NN - 1);
    const float inv = g_inv[nc];

    {
        const uint4* fr4 = (const uint4*)(fin + (size_t)nc * 32);
        u32* aF = A_F + tid * 36;
#pragma unroll
        for (int q = 0; q < 8; ++q) *(uint4*)(aF + 4 * q) = fr4[q];

        const float4* fm = (const float4*)(g_msg + (size_t)nc * 64);
        u32* aM = A_M + tid * 36;
#pragma unroll
        for (int q = 0; q < 16; ++q) {
            float4 v = fm[q];
            aM[2 * q]     = pk2(v.x * inv, v.y * inv);
            aM[2 * q + 1] = pk2(v.z * inv, v.w * inv);
        }
    }
    if (valid) {
        float4* fm = (float4*)(g_msg + (size_t)n * 64);
        const float4 z4 = make_float4(0.f, 0.f, 0.f, 0.f);
#pragma unroll
        for (int q = 0; q < 16; ++q) fm[q] = z4;
        if (DO_POS) {
            posOut[n * 3 + 0] = posIn[n * 3 + 0] + g_pagg[n * 3 + 0] * inv;
            posOut[n * 3 + 1] = posIn[n * 3 + 1] + g_pagg[n * 3 + 1] * inv;
            posOut[n * 3 + 2] = posIn[n * 3 + 2] + g_pagg[n * 3 + 2] * inv;
            g_pagg[n * 3 + 0] = 0.f;
            g_pagg[n * 3 + 1] = 0.f;
            g_pagg[n * 3 + 2] = 0.f;
        }
    }
    __syncwarp();

    float acc[2][8][4];
#pragma unroll
    for (int mt = 0; mt < 2; ++mt)
#pragma unroll
        for (int nt = 0; nt < 8; ++nt)
#pragma unroll
            for (int i = 0; i < 4; ++i) acc[mt][nt][i] = 0.0f;

#pragma unroll
    for (int kt = 0; kt < 4; ++kt) stepK(acc, A_F, N1s, 36, 68, kt * 8, kt * 8, tb, g, cc);
#pragma unroll
    for (int kt = 0; kt < 4; ++kt) stepK(acc, A_M, N1s, 36, 68, kt * 8, 32 + kt * 8, tb, g, cc);

#pragma unroll
    for (int mt = 0; mt < 2; ++mt) {
        const int e0 = tb + mt * 16 + g, e1 = e0 + 8;
#pragma unroll
        for (int nt = 0; nt < 8; ++nt) {
            const int n0 = nt * 8 + 2 * cc;
            float v00 = silu_f(acc[mt][nt][0] + b1s[n0]);
            float v01 = silu_f(acc[mt][nt][1] + b1s[n0 + 1]);
            float v10 = silu_f(acc[mt][nt][2] + b1s[n0]);
            float v11 = silu_f(acc[mt][nt][3] + b1s[n0 + 1]);
            const int word = nt * 4 + cc;
            A_F[e0 * 36 + word] = pk2(v00, v01);
            A_F[e1 * 36 + word] = pk2(v10, v11);
        }
    }
    __syncwarp();

#pragma unroll
    for (int mt = 0; mt < 2; ++mt)
#pragma unroll
        for (int nt = 0; nt < 8; ++nt)
#pragma unroll
            for (int i = 0; i < 4; ++i) acc[mt][nt][i] = 0.0f;
#pragma unroll
    for (int kt = 0; kt < 4; ++kt) stepK(acc, A_F, N2s, 36, 36, kt * 8, kt * 8, tb, g, cc);

#pragma unroll
    for (int mt = 0; mt < 2; ++mt) {
        const int m0 = tile * ETPB + tb + mt * 16 + g;
        const int m1 = m0 + 8;
#pragma unroll
        for (int nt = 0; nt < 8; ++nt) {
            const int n0 = nt * 8 + 2 * cc;
            const int word = nt * 4 + cc;
            if (m0 < NN)
                fout[(size_t)m0 * 32 + word] = pk2(acc[mt][nt][0] + b2s[n0], acc[mt][nt][1] + b2s[n0 + 1]);
            if (m1 < NN)
                fout[(size_t)m1 * 32 + word] = pk2(acc[mt][nt][2] + b2s[n0], acc[mt][nt][3] + b2s[n0 + 1]);
        }
    }
}

// ================= helper kernels =================
__global__ void init_kernel(const float* __restrict__ pos) {
    int i = blockIdx.x * blockDim.x + threadIdx.x;
    if (i < NN * 64) g_msg[i] = 0.0f;
    if (i < NN * 3) { g_pagg[i] = 0.0f; g_posB[i] = pos[i]; }
    if (i < NN) g_cnt[i] = 0;
}
__global__ void count_kernel(const int* __restrict__ row) {
    int e = blockIdx.x * blockDim.x + threadIdx.x;
    if (e < EE) atomicAdd(&g_cnt[row[e]], 1);
}
__global__ void prep_kernel(const float* __restrict__ nf, const float* __restrict__ embW,
                            const float* __restrict__ embb,
                            const float* __restrict__ mW1, const float* __restrict__ mW2,
                            const float* __restrict__ pW1,
                            const float* __restrict__ nW1, const float* __restrict__ nW2) {
    int i = blockIdx.x * blockDim.x + threadIdx.x;
    if (i < NN) g_inv[i] = 1.0f / fmaxf((float)g_cnt[i], 1.0f);
    if (i < NN * 32) {
        int n = i >> 5, w = i & 31;
        int J = 2 * w;
        float v0 = nf[2 * n] * embW[J] + nf[2 * n + 1] * embW[64 + J] + embb[J];
        float v1 = nf[2 * n] * embW[J + 1] + nf[2 * n + 1] * embW[64 + J + 1] + embb[J + 1];
        g_featPA[i] = pk2(v0, v1);
    }
    if (i < 5 * 8192) {
        int l = i >> 13, rem = i & 8191;
        u32 out;
        if (rem < 4096) {
            int n = rem >> 6, w = rem & 63;
            int k = 2 * w;
            out = pk2(mW1[l * 131 * 64 + k * 64 + n], mW1[l * 131 * 64 + (k + 1) * 64 + n]);
        } else {
            int rem2 = rem - 4096;
            int mat = rem2 >> 11, idx = rem2 & 2047;
            int n = idx >> 5, w = idx & 31;
            int k = 2 * w;
            const float* src = (mat == 0) ? mW2 : pW1;
            out = pk2(src[l * 4096 + k * 64 + n], src[l * 4096 + (k + 1) * 64 + n]);
        }
        g_wb[i] = out;
    }
    if (i < 5 * 6144) {
        int l = i / 6144, rem = i % 6144;
        u32 out;
        if (rem < 4096) {
            int n = rem >> 6, w = rem & 63;
            int k = 2 * w;
            out = pk2(nW1[l * 8192 + k * 64 + n], nW1[l * 8192 + (k + 1) * 64 + n]);
        } else {
            int idx = rem - 4096;
            int n = idx >> 5, w = idx & 31;
            int k = 2 * w;
            out = pk2(nW2[l * 4096 + k * 64 + n], nW2[l * 4096 + (k + 1) * 64 + n]);
        }
        g_wnb[i] = out;
    }
}
__global__ void pos_final_kernel(float* __restrict__ out) {
    int i = blockIdx.x * blockDim.x + threadIdx.x;
    if (i < NN * 3) {
        int n = i / 3;
        out[i] = g_posA[i] + g_pagg[i] * g_inv[n];
    }
}

extern "C" void kernel_launch(void* const* d_in, const int* in_sizes, int n_in,
                              void* d_out, int out_size)
{
    const float*  node_feat = (const float*)d_in[0];
    const float*  node_pos  = (const float*)d_in[1];
    const float2* edge_attr = (const float2*)d_in[2];
    const int*    row       = (const int*)d_in[3];
    const int*    col       = (const int*)d_in[4];
    const float*  emb_W     = (const float*)d_in[5];
    const float*  emb_b     = (const float*)d_in[6];
    const float*  mW1 = (const float*)d_in[7];
    const float*  mb1 = (const float*)d_in[8];
    const float*  mW2 = (const float*)d_in[9];
    const float*  mb2 = (const float*)d_in[10];
    const float*  pW1 = (const float*)d_in[11];
    const float*  pb1 = (const float*)d_in[12];
    const float*  pW2 = (const float*)d_in[13];
    const float*  pb2 = (const float*)d_in[14];
    const float*  nW1 = (const float*)d_in[15];
    const float*  nb1 = (const float*)d_in[16];
    const float*  nW2 = (const float*)d_in[17];
    const float*  nb2 = (const float*)d_in[18];
    float* out = (float*)d_out;

    cudaFuncSetAttribute(edge_kernel<true, false>, cudaFuncAttributeMaxDynamicSharedMemorySize, SM_TOT);
    cudaFuncSetAttribute(edge_kernel<true, true>,  cudaFuncAttributeMaxDynamicSharedMemorySize, SM_TOT);
    cudaFuncSetAttribute(edge_kernel<false, true>, cudaFuncAttributeMaxDynamicSharedMemorySize, SM_TOT);
    cudaFuncSetAttribute(node_mma_kernel<false>, cudaFuncAttributeMaxDynamicSharedMemorySize, NSM_TOT);
    cudaFuncSetAttribute(node_mma_kernel<true>,  cudaFuncAttributeMaxDynamicSharedMemorySize, NSM_TOT);

    const int ZG = (NN * 64 + 255) / 256;

    init_kernel<<<ZG, 256>>>(node_pos);
    count_kernel<<<(EE + 255) / 256, 256>>>(row);
    prep_kernel<<<ZG, 256>>>(node_feat, emb_W, emb_b, mW1, mW2, pW1, nW1, nW2);

#define EDGE_ARGS(l) edge_attr, row, col, \
        mW1 + (l) * 131 * 64, mb1 + (l) * 64, mb2 + (l) * 64, \
        pb1 + (l) * 64, pW2 + (l) * 64, pb2 + (l)

    // L0 (com_node_feat_net): feat only
    edge_kernel<true, false><<<EGRID, ETPB, SM_TOT>>>(0, 1, 0, EDGE_ARGS(0));
    node_mma_kernel<false><<<NTTILES, ETPB, NSM_TOT>>>(0, 1, 0, nb1 + 0, nb2 + 0);
    // L1
    edge_kernel<true, true><<<EGRID, ETPB, SM_TOT>>>(1, 1, 1, EDGE_ARGS(1));
    node_mma_kernel<true><<<NTTILES, ETPB, NSM_TOT>>>(1, 1, 1, nb1 + 64, nb2 + 64);
    // L2
    edge_kernel<true, true><<<EGRID, ETPB, SM_TOT>>>(0, 0, 2, EDGE_ARGS(2));
    node_mma_kernel<true><<<NTTILES, ETPB, NSM_TOT>>>(0, 0, 2, nb1 + 128, nb2 + 128);
    // L3
    edge_kernel<true, true><<<EGRID, ETPB, SM_TOT>>>(1, 1, 3, EDGE_ARGS(3));
    node_mma_kernel<true><<<NTTILES, ETPB, NSM_TOT>>>(1, 1, 3, nb1 + 192, nb2 + 192);
    // L4: pos only
    edge_kernel<false, true><<<EGRID, ETPB, SM_TOT>>>(0, 0, 4, EDGE_ARGS(4));
    pos_final_kernel<<<(NN * 3 + 255) / 256, 256>>>(out);

#undef EDGE_ARGS
}

// round 16
// speedup vs baseline: 1.3268x; 1.0318x over previous
#include <cuda_runtime.h>
#include <cstdint>

#define NN 50000
#define EE 800000
#define ETPB 256
#define NTILES 3125        // EE / 256 exactly
#define EGRID 296
#define NTTILES 196        // ceil(NN / 256)

typedef unsigned long long ull;
typedef unsigned int u32;

// -------- persistent device scratch --------
__device__ u32   g_featPA[NN * 32];
__device__ u32   g_featPB[NN * 32];
__device__ float g_posA[NN * 3];
__device__ float g_posB[NN * 3];
__device__ float g_msg[NN * 64];
__device__ float g_pagg[NN * 3];
__device__ float g_inv[NN];
__device__ int   g_cnt[NN];
__device__ u32   g_wb[5 * 8192];   // edge weights, k-permuted pairs
__device__ u32   g_wnb[5 * 6144];  // node weights, k-permuted pairs

// -------- helpers --------
// silu via tanh: silu(x) = hx + hx*tanh(hx), hx = x/2.  1 MUFU + 1 MUL + 1 FMA.
__device__ __forceinline__ float silu_f(float x) {
    float hx = 0.5f * x;
    float t;
    asm("tanh.approx.f32 %0, %1;" : "=f"(t) : "f"(hx));
    return hx + hx * t;
}
__device__ __forceinline__ u32 pk2(float lo, float hi) {
    u32 r;
    asm("cvt.rn.bf16x2.f32 %0, %1, %2;" : "=r"(r) : "f"(hi), "f"(lo));
    return r;
}

#define MMAB(d, a0, a1, a2, a3, b0, b1)                                            \
    asm volatile("mma.sync.aligned.m16n8k16.row.col.f32.bf16.bf16.f32 "            \
                 "{%0,%1,%2,%3}, {%4,%5,%6,%7}, {%8,%9}, {%0,%1,%2,%3};"           \
                 : "+f"((d)[0]), "+f"((d)[1]), "+f"((d)[2]), "+f"((d)[3])          \
                 : "r"(a0), "r"(a1), "r"(a2), "r"(a3), "r"(b0), "r"(b1))

#define REDV2(p, a, b)                                                             \
    asm volatile("red.global.add.v2.f32 [%0], {%1, %2};" :: "l"(p), "f"(a), "f"(b) : "memory")

#define SHF(v, src) __shfl_sync(0xffffffffu, (v), (src))

// one k16 step: 16 MMAs; B fragments = single LDS.64 (k-permuted weights), A scalar (natural)
__device__ __forceinline__ void stepK(float acc[2][8][4], const u32* A, const u32* B,
                                      int Astride, int Bstride, int kwA, int kwB,
                                      int tb, int g, int cc)
{
    u32 b0[8], b1[8];
#pragma unroll
    for (int nt = 0; nt < 8; ++nt) {
        uint2 bv = *(const uint2*)(B + (nt * 8 + g) * Bstride + kwB + 2 * cc);
        b0[nt] = bv.x;
        b1[nt] = bv.y;
    }
#pragma unroll
    for (int mt = 0; mt < 2; ++mt) {
        const u32* ar = A + (tb + mt * 16 + g) * Astride + kwA;
        u32 a0 = ar[cc];
        u32 a1 = ar[8 * Astride + cc];
        u32 a2 = ar[4 + cc];
        u32 a3 = ar[8 * Astride + 4 + cc];
#pragma unroll
        for (int nt = 0; nt < 8; ++nt)
            MMAB(acc[mt][nt], a0, a1, a2, a3, b0[nt], b1[nt]);
    }
}

// -------- edge kernel SMEM layout (permuted-weight strides 72/40) --------
#define O_W1   0        // 64 x 72w = 18432
#define O_W2   18432    // 64 x 40w = 10240
#define O_P1   28672    // 64 x 40w = 10240
#define O_AR   38912    // 256 x 36w = 36864
#define O_AC   75776    // 256 x 36w = 36864
#define O_SXT  112640   // 1024
#define O_SB2  113664   // 256
#define O_SXP  113920   // 512
#define SM_TOT 114432

template <bool DO_MSG, bool DO_POS>
__global__ void __launch_bounds__(ETPB, 2)
edge_kernel(int featSel, int posSel, int layer,
            const float2* __restrict__ ea_g,
            const int* __restrict__ row, const int* __restrict__ col,
            const float* __restrict__ mW1, const float* __restrict__ mb1,
            const float* __restrict__ mb2, const float* __restrict__ pb1,
            const float* __restrict__ pW2, const float* __restrict__ pb2)
{
    extern __shared__ __align__(16) char sm[];
    u32*    W1s  = (u32*)(sm + O_W1);
    u32*    W2s  = (u32*)(sm + O_W2);
    u32*    P1s  = (u32*)(sm + O_P1);
    u32*    A_R  = (u32*)(sm + O_AR);
    u32*    A_C  = (u32*)(sm + O_AC);
    float4* sxT  = (float4*)(sm + O_SXT);
    float*  sxB2 = (float*)(sm + O_SB2);
    float2* sxP  = (float2*)(sm + O_SXP);

    const int tid = threadIdx.x;

    {
        const u32* wsrc = g_wb + layer * 8192;
        for (int i = tid; i < 4096; i += ETPB) {
            int n = i >> 6, w = i & 63;
            W1s[n * 72 + w] = wsrc[i];
        }
        for (int i = tid; i < 2048; i += ETPB) {
            int n = i >> 5, w = i & 31;
            W2s[n * 40 + w] = wsrc[4096 + i];
            P1s[n * 40 + w] = wsrc[6144 + i];
        }
    }
    if (tid < 64) {
        sxT[tid] = make_float4(mW1[128 * 64 + tid], mW1[129 * 64 + tid], mW1[130 * 64 + tid], mb1[tid]);
        sxB2[tid] = mb2[tid];
        sxP[tid] = make_float2(pb1[tid], pW2[tid]);
    }
    const float pb2v = pb2[0];
    __syncthreads();

    const u32* featP = featSel ? g_featPB : g_featPA;
    const float* posIn = posSel ? g_posB : g_posA;

    const int lane = tid & 31;
    const int g  = lane >> 2;
    const int cc = lane & 3;
    const int tb = (tid >> 5) * 32;
    const int sub   = lane >> 3;   // gather: which row of the 4-row pass
    const int chunk = lane & 7;    // gather: 16B chunk within the 128B row

    for (int tile = blockIdx.x; tile < NTILES; tile += gridDim.x) {
        __syncwarp();
        const int e = tile * ETPB + tid;
        const int r = row[e], c = col[e];
        const float dx = posIn[r * 3 + 0] - posIn[c * 3 + 0];
        const float dy = posIn[r * 3 + 1] - posIn[c * 3 + 1];
        const float dz = posIn[r * 3 + 2] - posIn[c * 3 + 2];
        const float dist = dx * dx + dy * dy + dz * dz;
        const float2 ea = ea_g[e];

        // warp-cooperative gather: 8 lanes load one full 128B feat row
#pragma unroll
        for (int p = 0; p < 8; ++p) {
            const int q = p * 4 + sub;
            const int rq = SHF(r, q);
            const int cq = SHF(c, q);
            *(uint4*)(A_R + (tb + q) * 36 + chunk * 4) =
                *(const uint4*)(featP + (size_t)rq * 32 + chunk * 4);
            *(uint4*)(A_C + (tb + q) * 36 + chunk * 4) =
                *(const uint4*)(featP + (size_t)cq * 32 + chunk * 4);
        }
        __syncwarp();

        float acc[2][8][4];
#pragma unroll
        for (int mt = 0; mt < 2; ++mt)
#pragma unroll
            for (int nt = 0; nt < 8; ++nt)
#pragma unroll
                for (int i = 0; i < 4; ++i) acc[mt][nt][i] = 0.0f;

        // ---- stage 1 ----
#pragma unroll
        for (int kt = 0; kt < 4; ++kt) stepK(acc, A_R, W1s, 36, 72, kt * 8, kt * 8, tb, g, cc);
#pragma unroll
        for (int kt = 0; kt < 4; ++kt) stepK(acc, A_C, W1s, 36, 72, kt * 8, 32 + kt * 8, tb, g, cc);

        // ---- epilogue 1 ----
#pragma unroll
        for (int mt = 0; mt < 2; ++mt) {
            const int q0 = mt * 16 + g, q1 = q0 + 8;
            const float ex0 = SHF(ea.x, q0), ey0 = SHF(ea.y, q0), ds0 = SHF(dist, q0);
            const float ex1 = SHF(ea.x, q1), ey1 = SHF(ea.y, q1), ds1 = SHF(dist, q1);
            const int e0 = tb + q0, e1 = tb + q1;
#pragma unroll
            for (int nt = 0; nt < 8; ++nt) {
                const int n0 = nt * 8 + 2 * cc;
                const float4 t0 = sxT[n0], t1 = sxT[n0 + 1];
                float v00 = silu_f(acc[mt][nt][0] + t0.w + ex0 * t0.x + ey0 * t0.y + ds0 * t0.z);
                float v01 = silu_f(acc[mt][nt][1] + t1.w + ex0 * t1.x + ey0 * t1.y + ds0 * t1.z);
                float v10 = silu_f(acc[mt][nt][2] + t0.w + ex1 * t0.x + ey1 * t0.y + ds1 * t0.z);
                float v11 = silu_f(acc[mt][nt][3] + t1.w + ex1 * t1.x + ey1 * t1.y + ds1 * t1.z);
                const int word = nt * 4 + cc;
                A_R[e0 * 36 + word] = pk2(v00, v01);
                A_R[e1 * 36 + word] = pk2(v10, v11);
            }
        }
        __syncwarp();

        // ---- stage 2 ----
#pragma unroll
        for (int mt = 0; mt < 2; ++mt)
#pragma unroll
            for (int nt = 0; nt < 8; ++nt)
#pragma unroll
                for (int i = 0; i < 4; ++i) acc[mt][nt][i] = 0.0f;
#pragma unroll
        for (int kt = 0; kt < 4; ++kt) stepK(acc, A_R, W2s, 36, 40, kt * 8, kt * 8, tb, g, cc);

        // ---- epilogue 2 ----
        int r0s[2], r1s[2];
#pragma unroll
        for (int mt = 0; mt < 2; ++mt) {
            const int q0 = mt * 16 + g, q1 = q0 + 8;
            const int r0 = SHF(r, q0), r1 = SHF(r, q1);
            r0s[mt] = r0; r1s[mt] = r1;
            const int e0 = tb + q0, e1 = tb + q1;
#pragma unroll
            for (int nt = 0; nt < 8; ++nt) {
                const int n0 = nt * 8 + 2 * cc;
                float m00 = silu_f(acc[mt][nt][0] + sxB2[n0]);
                float m01 = silu_f(acc[mt][nt][1] + sxB2[n0 + 1]);
                float m10 = silu_f(acc[mt][nt][2] + sxB2[n0]);
                float m11 = silu_f(acc[mt][nt][3] + sxB2[n0 + 1]);
                if (DO_MSG) {
                    REDV2(g_msg + (size_t)r0 * 64 + n0, m00, m01);
                    REDV2(g_msg + (size_t)r1 * 64 + n0, m10, m11);
                }
                if (DO_POS) {
                    const int word = nt * 4 + cc;
                    A_C[e0 * 36 + word] = pk2(m00, m01);
                    A_C[e1 * 36 + word] = pk2(m10, m11);
                }
            }
        }

        if (DO_POS) {
            __syncwarp();
            // ---- stage 3 ----
#pragma unroll
            for (int mt = 0; mt < 2; ++mt)
#pragma unroll
                for (int nt = 0; nt < 8; ++nt)
#pragma unroll
                    for (int i = 0; i < 4; ++i) acc[mt][nt][i] = 0.0f;
#pragma unroll
            for (int kt = 0; kt < 4; ++kt) stepK(acc, A_C, P1s, 36, 40, kt * 8, kt * 8, tb, g, cc);

            // ---- epilogue 3 ----
#pragma unroll
            for (int mt = 0; mt < 2; ++mt) {
                const int q0 = mt * 16 + g, q1 = q0 + 8;
                float w0 = 0.0f, w1 = 0.0f;
#pragma unroll
                for (int nt = 0; nt < 8; ++nt) {
                    const int n0 = nt * 8 + 2 * cc;
                    const float2 p0 = sxP[n0], p1 = sxP[n0 + 1];
                    w0 += silu_f(acc[mt][nt][0] + p0.x) * p0.y + silu_f(acc[mt][nt][1] + p1.x) * p1.y;
                    w1 += silu_f(acc[mt][nt][2] + p0.x) * p0.y + silu_f(acc[mt][nt][3] + p1.x) * p1.y;
                }
                w0 += __shfl_xor_sync(0xffffffffu, w0, 1);
                w0 += __shfl_xor_sync(0xffffffffu, w0, 2);
                w1 += __shfl_xor_sync(0xffffffffu, w1, 1);
                w1 += __shfl_xor_sync(0xffffffffu, w1, 2);
                const float dx0 = SHF(dx, q0), dy0 = SHF(dy, q0), dz0 = SHF(dz, q0);
                const float dx1 = SHF(dx, q1), dy1 = SHF(dy, q1), dz1 = SHF(dz, q1);
                if (cc == 0) {
                    const int r0 = r0s[mt], r1 = r1s[mt];
                    const float wa = w0 + pb2v, wb = w1 + pb2v;
                    atomicAdd(&g_pagg[r0 * 3 + 0], dx0 * wa);
                    atomicAdd(&g_pagg[r0 * 3 + 1], dy0 * wa);
                    atomicAdd(&g_pagg[r0 * 3 + 2], dz0 * wa);
                    atomicAdd(&g_pagg[r1 * 3 + 0], dx1 * wb);
                    atomicAdd(&g_pagg[r1 * 3 + 1], dy1 * wb);
                    atomicAdd(&g_pagg[r1 * 3 + 2], dz1 * wb);
                }
            }
        }
    }
}

// -------- node MMA kernel (permuted weights, tanh silu) --------
#define NO_W1  0        // 64 x 72w = 18432
#define NO_W2  18432    // 64 x 40w = 10240
#define NO_AF  28672    // 36864
#define NO_AM  65536    // 36864
#define NO_B1  102400   // 256
#define NO_B2  102656   // 256
#define NSM_TOT 102912

template <bool DO_POS>
__global__ void __launch_bounds__(ETPB, 2)
node_mma_kernel(int featSel, int posSel, int layer,
                const float* __restrict__ nb1, const float* __restrict__ nb2)
{
    extern __shared__ __align__(16) char sm[];
    u32*   N1s = (u32*)(sm + NO_W1);
    u32*   N2s = (u32*)(sm + NO_W2);
    u32*   A_F = (u32*)(sm + NO_AF);
    u32*   A_M = (u32*)(sm + NO_AM);
    float* b1s = (float*)(sm + NO_B1);
    float* b2s = (float*)(sm + NO_B2);

    const int tid = threadIdx.x;

    {
        const u32* wsrc = g_wnb + layer * 6144;
        for (int i = tid; i < 4096; i += ETPB) {
            int n = i >> 6, w = i & 63;
            N1s[n * 72 + w] = wsrc[i];
        }
        for (int i = tid; i < 2048; i += ETPB) {
            int n = i >> 5, w = i & 31;
            N2s[n * 40 + w] = wsrc[4096 + i];
        }
    }
    if (tid < 64) { b1s[tid] = nb1[tid]; b2s[tid] = nb2[tid]; }
    __syncthreads();

    const u32* fin  = featSel ? g_featPB : g_featPA;
    u32*       fout = featSel ? g_featPA : g_featPB;
    const float* posIn  = posSel ? g_posB : g_posA;
    float*       posOut = posSel ? g_posA : g_posB;

    const int lane = tid & 31;
    const int g  = lane >> 2;
    const int cc = lane & 3;
    const int tb = (tid >> 5) * 32;

    const int tile = blockIdx.x;
    const int n = tile * ETPB + tid;
    const bool valid = (n < NN);
    const int nc = valid ? n : (NN - 1);
    const float inv = g_inv[nc];

    {
        const uint4* fr4 = (const uint4*)(fin + (size_t)nc * 32);
        u32* aF = A_F + tid * 36;
#pragma unroll
        for (int q = 0; q < 8; ++q) *(uint4*)(aF + 4 * q) = fr4[q];

        const float4* fm = (const float4*)(g_msg + (size_t)nc * 64);
        u32* aM = A_M + tid * 36;
#pragma unroll
        for (int q = 0; q < 16; ++q) {
            float4 v = fm[q];
            aM[2 * q]     = pk2(v.x * inv, v.y * inv);
            aM[2 * q + 1] = pk2(v.z * inv, v.w * inv);
        }
    }
    if (valid) {
        float4* fm = (float4*)(g_msg + (size_t)n * 64);
        const float4 z4 = make_float4(0.f, 0.f, 0.f, 0.f);
#pragma unroll
        for (int q = 0; q < 16; ++q) fm[q] = z4;
        if (DO_POS) {
            posOut[n * 3 + 0] = posIn[n * 3 + 0] + g_pagg[n * 3 + 0] * inv;
            posOut[n * 3 + 1] = posIn[n * 3 + 1] + g_pagg[n * 3 + 1] * inv;
            posOut[n * 3 + 2] = posIn[n * 3 + 2] + g_pagg[n * 3 + 2] * inv;
            g_pagg[n * 3 + 0] = 0.f;
            g_pagg[n * 3 + 1] = 0.f;
            g_pagg[n * 3 + 2] = 0.f;
        }
    }
    __syncwarp();

    float acc[2][8][4];
#pragma unroll
    for (int mt = 0; mt < 2; ++mt)
#pragma unroll
        for (int nt = 0; nt < 8; ++nt)
#pragma unroll
            for (int i = 0; i < 4; ++i) acc[mt][nt][i] = 0.0f;

#pragma unroll
    for (int kt = 0; kt < 4; ++kt) stepK(acc, A_F, N1s, 36, 72, kt * 8, kt * 8, tb, g, cc);
#pragma unroll
    for (int kt = 0; kt < 4; ++kt) stepK(acc, A_M, N1s, 36, 72, kt * 8, 32 + kt * 8, tb, g, cc);

#pragma unroll
    for (int mt = 0; mt < 2; ++mt) {
        const int e0 = tb + mt * 16 + g, e1 = e0 + 8;
#pragma unroll
        for (int nt = 0; nt < 8; ++nt) {
            const int n0 = nt * 8 + 2 * cc;
            float v00 = silu_f(acc[mt][nt][0] + b1s[n0]);
            float v01 = silu_f(acc[mt][nt][1] + b1s[n0 + 1]);
            float v10 = silu_f(acc[mt][nt][2] + b1s[n0]);
            float v11 = silu_f(acc[mt][nt][3] + b1s[n0 + 1]);
            const int word = nt * 4 + cc;
            A_F[e0 * 36 + word] = pk2(v00, v01);
            A_F[e1 * 36 + word] = pk2(v10, v11);
        }
    }
    __syncwarp();

#pragma unroll
    for (int mt = 0; mt < 2; ++mt)
#pragma unroll
        for (int nt = 0; nt < 8; ++nt)
#pragma unroll
            for (int i = 0; i < 4; ++i) acc[mt][nt][i] = 0.0f;
#pragma unroll
    for (int kt = 0; kt < 4; ++kt) stepK(acc, A_F, N2s, 36, 40, kt * 8, kt * 8, tb, g, cc);

#pragma unroll
    for (int mt = 0; mt < 2; ++mt) {
        const int m0 = tile * ETPB + tb + mt * 16 + g;
        const int m1 = m0 + 8;
#pragma unroll
        for (int nt = 0; nt < 8; ++nt) {
            const int n0 = nt * 8 + 2 * cc;
            const int word = nt * 4 + cc;
            if (m0 < NN)
                fout[(size_t)m0 * 32 + word] = pk2(acc[mt][nt][0] + b2s[n0], acc[mt][nt][1] + b2s[n0 + 1]);
            if (m1 < NN)
                fout[(size_t)m1 * 32 + word] = pk2(acc[mt][nt][2] + b2s[n0], acc[mt][nt][3] + b2s[n0 + 1]);
        }
    }
}

// ================= helper kernels =================
__global__ void init_kernel(const float* __restrict__ pos) {
    int i = blockIdx.x * blockDim.x + threadIdx.x;
    if (i < NN * 64) g_msg[i] = 0.0f;
    if (i < NN * 3) { g_pagg[i] = 0.0f; g_posB[i] = pos[i]; }
    if (i < NN) g_cnt[i] = 0;
}
__global__ void count_kernel(const int* __restrict__ row) {
    int e = blockIdx.x * blockDim.x + threadIdx.x;
    if (e < EE) atomicAdd(&g_cnt[row[e]], 1);
}
// k-permuted weight position: p = P&7; k = 16*(P>>3) + (p odd ? p+7 : p)
__global__ void prep_kernel(const float* __restrict__ nf, const float* __restrict__ embW,
                            const float* __restrict__ embb,
                            const float* __restrict__ mW1, const float* __restrict__ mW2,
                            const float* __restrict__ pW1,
                            const float* __restrict__ nW1, const float* __restrict__ nW2) {
    int i = blockIdx.x * blockDim.x + threadIdx.x;
    if (i < NN) g_inv[i] = 1.0f / fmaxf((float)g_cnt[i], 1.0f);
    if (i < NN * 32) {
        int n = i >> 5, w = i & 31;
        int J = 2 * w;
        float v0 = nf[2 * n] * embW[J] + nf[2 * n + 1] * embW[64 + J] + embb[J];
        float v1 = nf[2 * n] * embW[J + 1] + nf[2 * n + 1] * embW[64 + J + 1] + embb[J + 1];
        g_featPA[i] = pk2(v0, v1);
    }
    if (i < 5 * 8192) {
        int l = i >> 13, rem = i & 8191;
        u32 out;
        if (rem < 4096) {
            int n = rem >> 6, P = rem & 63;
            int p = P & 7;
            int k = 16 * (P >> 3) + ((p & 1) ? p + 7 : p);
            out = pk2(mW1[l * 131 * 64 + k * 64 + n], mW1[l * 131 * 64 + (k + 1) * 64 + n]);
        } else {
            int rem2 = rem - 4096;
            int mat = rem2 >> 11, idx = rem2 & 2047;
            int n = idx >> 5, P = idx & 31;
            int p = P & 7;
            int k = 16 * (P >> 3) + ((p & 1) ? p + 7 : p);
            const float* src = (mat == 0) ? mW2 : pW1;
            out = pk2(src[l * 4096 + k * 64 + n], src[l * 4096 + (k + 1) * 64 + n]);
        }
        g_wb[i] = out;
    }
    if (i < 5 * 6144) {
        int l = i / 6144, rem = i % 6144;
        u32 out;
        if (rem < 4096) {
            int n = rem >> 6, P = rem & 63;
            int p = P & 7;
            int k = 16 * (P >> 3) + ((p & 1) ? p + 7 : p);
            out = pk2(nW1[l * 8192 + k * 64 + n], nW1[l * 8192 + (k + 1) * 64 + n]);
        } else {
            int idx = rem - 4096;
            int n = idx >> 5, P = idx & 31;
            int p = P & 7;
            int k = 16 * (P >> 3) + ((p & 1) ? p + 7 : p);
            out = pk2(nW2[l * 4096 + k * 64 + n], nW2[l * 4096 + (k + 1) * 64 + n]);
        }
        g_wnb[i] = out;
    }
}
__global__ void pos_final_kernel(float* __restrict__ out) {
    int i = blockIdx.x * blockDim.x + threadIdx.x;
    if (i < NN * 3) {
        int n = i / 3;
        out[i] = g_posA[i] + g_pagg[i] * g_inv[n];
    }
}

extern "C" void kernel_launch(void* const* d_in, const int* in_sizes, int n_in,
                              void* d_out, int out_size)
{
    const float*  node_feat = (const float*)d_in[0];
    const float*  node_pos  = (const float*)d_in[1];
    const float2* edge_attr = (const float2*)d_in[2];
    const int*    row       = (const int*)d_in[3];
    const int*    col       = (const int*)d_in[4];
    const float*  emb_W     = (const float*)d_in[5];
    const float*  emb_b     = (const float*)d_in[6];
    const float*  mW1 = (const float*)d_in[7];
    const float*  mb1 = (const float*)d_in[8];
    const float*  mW2 = (const float*)d_in[9];
    const float*  mb2 = (const float*)d_in[10];
    const float*  pW1 = (const float*)d_in[11];
    const float*  pb1 = (const float*)d_in[12];
    const float*  pW2 = (const float*)d_in[13];
    const float*  pb2 = (const float*)d_in[14];
    const float*  nW1 = (const float*)d_in[15];
    const float*  nb1 = (const float*)d_in[16];
    const float*  nW2 = (const float*)d_in[17];
    const float*  nb2 = (const float*)d_in[18];
    float* out = (float*)d_out;

    cudaFuncSetAttribute(edge_kernel<true, false>, cudaFuncAttributeMaxDynamicSharedMemorySize, SM_TOT);
    cudaFuncSetAttribute(edge_kernel<true, true>,  cudaFuncAttributeMaxDynamicSharedMemorySize, SM_TOT);
    cudaFuncSetAttribute(edge_kernel<false, true>, cudaFuncAttributeMaxDynamicSharedMemorySize, SM_TOT);
    cudaFuncSetAttribute(node_mma_kernel<false>, cudaFuncAttributeMaxDynamicSharedMemorySize, NSM_TOT);
    cudaFuncSetAttribute(node_mma_kernel<true>,  cudaFuncAttributeMaxDynamicSharedMemorySize, NSM_TOT);

    const int ZG = (NN * 64 + 255) / 256;

    init_kernel<<<ZG, 256>>>(node_pos);
    count_kernel<<<(EE + 255) / 256, 256>>>(row);
    prep_kernel<<<ZG, 256>>>(node_feat, emb_W, emb_b, mW1, mW2, pW1, nW1, nW2);

#define EDGE_ARGS(l) edge_attr, row, col, \
        mW1 + (l) * 131 * 64, mb1 + (l) * 64, mb2 + (l) * 64, \
        pb1 + (l) * 64, pW2 + (l) * 64, pb2 + (l)

    // L0 (com_node_feat_net): feat only
    edge_kernel<true, false><<<EGRID, ETPB, SM_TOT>>>(0, 1, 0, EDGE_ARGS(0));
    node_mma_kernel<false><<<NTTILES, ETPB, NSM_TOT>>>(0, 1, 0, nb1 + 0, nb2 + 0);
    // L1
    edge_kernel<true, true><<<EGRID, ETPB, SM_TOT>>>(1, 1, 1, EDGE_ARGS(1));
    node_mma_kernel<true><<<NTTILES, ETPB, NSM_TOT>>>(1, 1, 1, nb1 + 64, nb2 + 64);
    // L2
    edge_kernel<true, true><<<EGRID, ETPB, SM_TOT>>>(0, 0, 2, EDGE_ARGS(2));
    node_mma_kernel<true><<<NTTILES, ETPB, NSM_TOT>>>(0, 0, 2, nb1 + 128, nb2 + 128);
    // L3
    edge_kernel<true, true><<<EGRID, ETPB, SM_TOT>>>(1, 1, 3, EDGE_ARGS(3));
    node_mma_kernel<true><<<NTTILES, ETPB, NSM_TOT>>>(1, 1, 3, nb1 + 192, nb2 + 192);
    // L4: pos only
    edge_kernel<false, true><<<EGRID, ETPB, SM_TOT>>>(0, 0, 4, EDGE_ARGS(4));
    pos_final_kernel<<<(NN * 3 + 255) / 256, 256>>>(out);

#undef EDGE_ARGS
}

// round 17
// speedup vs baseline: 1.3961x; 1.0522x over previous
#include <cuda_runtime.h>
#include <cstdint>

#define NN 50000
#define EE 800000
#define ETPB 256
#define NTILES 3125        // EE / 256 exactly
#define EGRID 296
#define NTTILES 196        // ceil(NN / 256)

typedef unsigned long long ull;
typedef unsigned int u32;

// -------- persistent device scratch --------
__device__ u32   g_featPA[NN * 32];
__device__ u32   g_featPB[NN * 32];
__device__ float g_posA[NN * 3];
__device__ float g_posB[NN * 3];
__device__ float g_msg[NN * 64];
__device__ float g_pagg[NN * 3];
__device__ float g_inv[NN];
__device__ int   g_cnt[NN];
__device__ u32   g_wb[5 * 8192];   // edge weights, k-permuted pairs
__device__ u32   g_wnb[5 * 6144];  // node weights, k-permuted pairs

// -------- helpers --------
// silu via tanh: silu(x) = hx + hx*tanh(hx), hx = x/2.  1 MUFU + 1 MUL + 1 FMA.
__device__ __forceinline__ float silu_f(float x) {
    float hx = 0.5f * x;
    float t;
    asm("tanh.approx.f32 %0, %1;" : "=f"(t) : "f"(hx));
    return hx + hx * t;
}
__device__ __forceinline__ u32 pk2(float lo, float hi) {
    u32 r;
    asm("cvt.rn.bf16x2.f32 %0, %1, %2;" : "=r"(r) : "f"(hi), "f"(lo));
    return r;
}

#define MMAB(d, a0, a1, a2, a3, b0, b1)                                            \
    asm volatile("mma.sync.aligned.m16n8k16.row.col.f32.bf16.bf16.f32 "            \
                 "{%0,%1,%2,%3}, {%4,%5,%6,%7}, {%8,%9}, {%0,%1,%2,%3};"           \
                 : "+f"((d)[0]), "+f"((d)[1]), "+f"((d)[2]), "+f"((d)[3])          \
                 : "r"(a0), "r"(a1), "r"(a2), "r"(a3), "r"(b0), "r"(b1))

#define REDV2(p, a, b)                                                             \
    asm volatile("red.global.add.v2.f32 [%0], {%1, %2};" :: "l"(p), "f"(a), "f"(b) : "memory")

#define SHF(v, src) __shfl_sync(0xffffffffu, (v), (src))

// one k16 step, A from SMEM (natural k-pair order), B = LDS.64 (k-permuted)
__device__ __forceinline__ void stepK(float acc[2][8][4], const u32* A, const u32* B,
                                      int Astride, int Bstride, int kwA, int kwB,
                                      int tb, int g, int cc)
{
    u32 b0[8], b1[8];
#pragma unroll
    for (int nt = 0; nt < 8; ++nt) {
        uint2 bv = *(const uint2*)(B + (nt * 8 + g) * Bstride + kwB + 2 * cc);
        b0[nt] = bv.x;
        b1[nt] = bv.y;
    }
#pragma unroll
    for (int mt = 0; mt < 2; ++mt) {
        const u32* ar = A + (tb + mt * 16 + g) * Astride + kwA;
        u32 a0 = ar[cc];
        u32 a1 = ar[8 * Astride + cc];
        u32 a2 = ar[4 + cc];
        u32 a3 = ar[8 * Astride + 4 + cc];
#pragma unroll
        for (int nt = 0; nt < 8; ++nt)
            MMAB(acc[mt][nt], a0, a1, a2, a3, b0[nt], b1[nt]);
    }
}

// one k16 step, A from REGISTERS (C-fragment of previous stage, packed bf16):
// au[mt][nt] = rows (g)   cols (nt*8+2cc, +1);  av[mt][nt] = rows (g+8), same cols.
// k-window kt uses groups 2kt (k 16kt+2cc) and 2kt+1 (k 16kt+8+2cc).
__device__ __forceinline__ void stepR(float acc[2][8][4],
                                      const u32 au[2][8], const u32 av[2][8],
                                      const u32* B, int Bstride, int kt, int g, int cc)
{
    u32 b0[8], b1[8];
#pragma unroll
    for (int nt = 0; nt < 8; ++nt) {
        uint2 bv = *(const uint2*)(B + (nt * 8 + g) * Bstride + kt * 8 + 2 * cc);
        b0[nt] = bv.x;
        b1[nt] = bv.y;
    }
#pragma unroll
    for (int mt = 0; mt < 2; ++mt) {
        u32 a0 = au[mt][2 * kt];
        u32 a1 = av[mt][2 * kt];
        u32 a2 = au[mt][2 * kt + 1];
        u32 a3 = av[mt][2 * kt + 1];
#pragma unroll
        for (int nt = 0; nt < 8; ++nt)
            MMAB(acc[mt][nt], a0, a1, a2, a3, b0[nt], b1[nt]);
    }
}

// -------- edge kernel SMEM layout (permuted-weight strides 72/40) --------
#define O_W1   0        // 64 x 72w = 18432
#define O_W2   18432    // 64 x 40w = 10240
#define O_P1   28672    // 64 x 40w = 10240
#define O_AR   38912    // 256 x 36w = 36864 (gather staging only)
#define O_AC   75776    // 256 x 36w = 36864 (gather staging only)
#define O_SXT  112640   // 1024
#define O_SB2  113664   // 256
#define O_SXP  113920   // 512
#define SM_TOT 114432

template <bool DO_MSG, bool DO_POS>
__global__ void __launch_bounds__(ETPB, 2)
edge_kernel(int featSel, int posSel, int layer,
            const float2* __restrict__ ea_g,
            const int* __restrict__ row, const int* __restrict__ col,
            const float* __restrict__ mW1, const float* __restrict__ mb1,
            const float* __restrict__ mb2, const float* __restrict__ pb1,
            const float* __restrict__ pW2, const float* __restrict__ pb2)
{
    extern __shared__ __align__(16) char sm[];
    u32*    W1s  = (u32*)(sm + O_W1);
    u32*    W2s  = (u32*)(sm + O_W2);
    u32*    P1s  = (u32*)(sm + O_P1);
    u32*    A_R  = (u32*)(sm + O_AR);
    u32*    A_C  = (u32*)(sm + O_AC);
    float4* sxT  = (float4*)(sm + O_SXT);
    float*  sxB2 = (float*)(sm + O_SB2);
    float2* sxP  = (float2*)(sm + O_SXP);

    const int tid = threadIdx.x;

    {
        const u32* wsrc = g_wb + layer * 8192;
        for (int i = tid; i < 4096; i += ETPB) {
            int n = i >> 6, w = i & 63;
            W1s[n * 72 + w] = wsrc[i];
        }
        for (int i = tid; i < 2048; i += ETPB) {
            int n = i >> 5, w = i & 31;
            W2s[n * 40 + w] = wsrc[4096 + i];
            P1s[n * 40 + w] = wsrc[6144 + i];
        }
    }
    if (tid < 64) {
        sxT[tid] = make_float4(mW1[128 * 64 + tid], mW1[129 * 64 + tid], mW1[130 * 64 + tid], mb1[tid]);
        sxB2[tid] = mb2[tid];
        sxP[tid] = make_float2(pb1[tid], pW2[tid]);
    }
    const float pb2v = pb2[0];
    __syncthreads();

    const u32* featP = featSel ? g_featPB : g_featPA;
    const float* posIn = posSel ? g_posB : g_posA;

    const int lane = tid & 31;
    const int g  = lane >> 2;
    const int cc = lane & 3;
    const int tb = (tid >> 5) * 32;
    const int sub   = lane >> 3;   // gather: which row of the 4-row pass
    const int chunk = lane & 7;    // gather: 16B chunk within the 128B row

    for (int tile = blockIdx.x; tile < NTILES; tile += gridDim.x) {
        __syncwarp();
        const int e = tile * ETPB + tid;
        const int r = row[e], c = col[e];
        const float dx = posIn[r * 3 + 0] - posIn[c * 3 + 0];
        const float dy = posIn[r * 3 + 1] - posIn[c * 3 + 1];
        const float dz = posIn[r * 3 + 2] - posIn[c * 3 + 2];
        const float dist = dx * dx + dy * dy + dz * dz;
        const float2 ea = ea_g[e];

        // warp-cooperative gather: 8 lanes load one full 128B feat row
#pragma unroll
        for (int p = 0; p < 8; ++p) {
            const int q = p * 4 + sub;
            const int rq = SHF(r, q);
            const int cq = SHF(c, q);
            *(uint4*)(A_R + (tb + q) * 36 + chunk * 4) =
                *(const uint4*)(featP + (size_t)rq * 32 + chunk * 4);
            *(uint4*)(A_C + (tb + q) * 36 + chunk * 4) =
                *(const uint4*)(featP + (size_t)cq * 32 + chunk * 4);
        }
        __syncwarp();

        float acc[2][8][4];
#pragma unroll
        for (int mt = 0; mt < 2; ++mt)
#pragma unroll
            for (int nt = 0; nt < 8; ++nt)
#pragma unroll
                for (int i = 0; i < 4; ++i) acc[mt][nt][i] = 0.0f;

        // ---- stage 1: h1_pre = featR @ W1[k 0:64] + featC @ W1[k 64:128] ----
#pragma unroll
        for (int kt = 0; kt < 4; ++kt) stepK(acc, A_R, W1s, 36, 72, kt * 8, kt * 8, tb, g, cc);
#pragma unroll
        for (int kt = 0; kt < 4; ++kt) stepK(acc, A_C, W1s, 36, 72, kt * 8, 32 + kt * 8, tb, g, cc);

        // ---- epilogue 1: tail + silu -> packed A-fragments in REGISTERS ----
        u32 au[2][8], av[2][8];
#pragma unroll
        for (int mt = 0; mt < 2; ++mt) {
            const int q0 = mt * 16 + g, q1 = q0 + 8;
            const float ex0 = SHF(ea.x, q0), ey0 = SHF(ea.y, q0), ds0 = SHF(dist, q0);
            const float ex1 = SHF(ea.x, q1), ey1 = SHF(ea.y, q1), ds1 = SHF(dist, q1);
#pragma unroll
            for (int nt = 0; nt < 8; ++nt) {
                const int n0 = nt * 8 + 2 * cc;
                const float4 t0 = sxT[n0], t1 = sxT[n0 + 1];
                float v00 = silu_f(acc[mt][nt][0] + t0.w + ex0 * t0.x + ey0 * t0.y + ds0 * t0.z);
                float v01 = silu_f(acc[mt][nt][1] + t1.w + ex0 * t1.x + ey0 * t1.y + ds0 * t1.z);
                float v10 = silu_f(acc[mt][nt][2] + t0.w + ex1 * t0.x + ey1 * t0.y + ds1 * t0.z);
                float v11 = silu_f(acc[mt][nt][3] + t1.w + ex1 * t1.x + ey1 * t1.y + ds1 * t1.z);
                au[mt][nt] = pk2(v00, v01);
                av[mt][nt] = pk2(v10, v11);
            }
        }

        // ---- stage 2: msg_pre = h1 @ W2 (A from registers) ----
#pragma unroll
        for (int mt = 0; mt < 2; ++mt)
#pragma unroll
            for (int nt = 0; nt < 8; ++nt)
#pragma unroll
                for (int i = 0; i < 4; ++i) acc[mt][nt][i] = 0.0f;
#pragma unroll
        for (int kt = 0; kt < 4; ++kt) stepR(acc, au, av, W2s, 40, kt, g, cc);

        // ---- epilogue 2: silu -> msg; RED scatter; packed msg A-fragments in regs ----
        int r0s[2], r1s[2];
#pragma unroll
        for (int mt = 0; mt < 2; ++mt) {
            const int q0 = mt * 16 + g, q1 = q0 + 8;
            const int r0 = SHF(r, q0), r1 = SHF(r, q1);
            r0s[mt] = r0; r1s[mt] = r1;
#pragma unroll
            for (int nt = 0; nt < 8; ++nt) {
                const int n0 = nt * 8 + 2 * cc;
                float m00 = silu_f(acc[mt][nt][0] + sxB2[n0]);
                float m01 = silu_f(acc[mt][nt][1] + sxB2[n0 + 1]);
                float m10 = silu_f(acc[mt][nt][2] + sxB2[n0]);
                float m11 = silu_f(acc[mt][nt][3] + sxB2[n0 + 1]);
                if (DO_MSG) {
                    REDV2(g_msg + (size_t)r0 * 64 + n0, m00, m01);
                    REDV2(g_msg + (size_t)r1 * 64 + n0, m10, m11);
                }
                if (DO_POS) {
                    au[mt][nt] = pk2(m00, m01);
                    av[mt][nt] = pk2(m10, m11);
                }
            }
        }

        if (DO_POS) {
            // ---- stage 3: p1_pre = msg @ PW1 (A from registers) ----
#pragma unroll
            for (int mt = 0; mt < 2; ++mt)
#pragma unroll
                for (int nt = 0; nt < 8; ++nt)
#pragma unroll
                    for (int i = 0; i < 4; ++i) acc[mt][nt][i] = 0.0f;
#pragma unroll
            for (int kt = 0; kt < 4; ++kt) stepR(acc, au, av, P1s, 40, kt, g, cc);

            // ---- epilogue 3 ----
#pragma unroll
            for (int mt = 0; mt < 2; ++mt) {
                const int q0 = mt * 16 + g, q1 = q0 + 8;
                float w0 = 0.0f, w1 = 0.0f;
#pragma unroll
                for (int nt = 0; nt < 8; ++nt) {
                    const int n0 = nt * 8 + 2 * cc;
                    const float2 p0 = sxP[n0], p1 = sxP[n0 + 1];
                    w0 += silu_f(acc[mt][nt][0] + p0.x) * p0.y + silu_f(acc[mt][nt][1] + p1.x) * p1.y;
                    w1 += silu_f(acc[mt][nt][2] + p0.x) * p0.y + silu_f(acc[mt][nt][3] + p1.x) * p1.y;
                }
                w0 += __shfl_xor_sync(0xffffffffu, w0, 1);
                w0 += __shfl_xor_sync(0xffffffffu, w0, 2);
                w1 += __shfl_xor_sync(0xffffffffu, w1, 1);
                w1 += __shfl_xor_sync(0xffffffffu, w1, 2);
                const float dx0 = SHF(dx, q0), dy0 = SHF(dy, q0), dz0 = SHF(dz, q0);
                const float dx1 = SHF(dx, q1), dy1 = SHF(dy, q1), dz1 = SHF(dz, q1);
                if (cc == 0) {
                    const int r0 = r0s[mt], r1 = r1s[mt];
                    const float wa = w0 + pb2v, wb = w1 + pb2v;
                    atomicAdd(&g_pagg[r0 * 3 + 0], dx0 * wa);
                    atomicAdd(&g_pagg[r0 * 3 + 1], dy0 * wa);
                    atomicAdd(&g_pagg[r0 * 3 + 2], dz0 * wa);
                    atomicAdd(&g_pagg[r1 * 3 + 0], dx1 * wb);
                    atomicAdd(&g_pagg[r1 * 3 + 1], dy1 * wb);
                    atomicAdd(&g_pagg[r1 * 3 + 2], dz1 * wb);
                }
            }
        }
    }
}

// -------- node MMA kernel (register inter-stage, permuted weights, tanh silu) --------
#define NO_W1  0        // 64 x 72w = 18432
#define NO_W2  18432    // 64 x 40w = 10240
#define NO_AF  28672    // 36864
#define NO_AM  65536    // 36864
#define NO_B1  102400   // 256
#define NO_B2  102656   // 256
#define NSM_TOT 102912

template <bool DO_POS>
__global__ void __launch_bounds__(ETPB, 2)
node_mma_kernel(int featSel, int posSel, int layer,
                const float* __restrict__ nb1, const float* __restrict__ nb2)
{
    extern __shared__ __align__(16) char sm[];
    u32*   N1s = (u32*)(sm + NO_W1);
    u32*   N2s = (u32*)(sm + NO_W2);
    u32*   A_F = (u32*)(sm + NO_AF);
    u32*   A_M = (u32*)(sm + NO_AM);
    float* b1s = (float*)(sm + NO_B1);
    float* b2s = (float*)(sm + NO_B2);

    const int tid = threadIdx.x;

    {
        const u32* wsrc = g_wnb + layer * 6144;
        for (int i = tid; i < 4096; i += ETPB) {
            int n = i >> 6, w = i & 63;
            N1s[n * 72 + w] = wsrc[i];
        }
        for (int i = tid; i < 2048; i += ETPB) {
            int n = i >> 5, w = i & 31;
            N2s[n * 40 + w] = wsrc[4096 + i];
        }
    }
    if (tid < 64) { b1s[tid] = nb1[tid]; b2s[tid] = nb2[tid]; }
    __syncthreads();

    const u32* fin  = featSel ? g_featPB : g_featPA;
    u32*       fout = featSel ? g_featPA : g_featPB;
    const float* posIn  = posSel ? g_posB : g_posA;
    float*       posOut = posSel ? g_posA : g_posB;

    const int lane = tid & 31;
    const int g  = lane >> 2;
    const int cc = lane & 3;
    const int tb = (tid >> 5) * 32;

    const int tile = blockIdx.x;
    const int n = tile * ETPB + tid;
    const bool valid = (n < NN);
    const int nc = valid ? n : (NN - 1);
    const float inv = g_inv[nc];

    {
        const uint4* fr4 = (const uint4*)(fin + (size_t)nc * 32);
        u32* aF = A_F + tid * 36;
#pragma unroll
        for (int q = 0; q < 8; ++q) *(uint4*)(aF + 4 * q) = fr4[q];

        const float4* fm = (const float4*)(g_msg + (size_t)nc * 64);
        u32* aM = A_M + tid * 36;
#pragma unroll
        for (int q = 0; q < 16; ++q) {
            float4 v = fm[q];
            aM[2 * q]     = pk2(v.x * inv, v.y * inv);
            aM[2 * q + 1] = pk2(v.z * inv, v.w * inv);
        }
    }
    if (valid) {
        float4* fm = (float4*)(g_msg + (size_t)n * 64);
        const float4 z4 = make_float4(0.f, 0.f, 0.f, 0.f);
#pragma unroll
        for (int q = 0; q < 16; ++q) fm[q] = z4;
        if (DO_POS) {
            posOut[n * 3 + 0] = posIn[n * 3 + 0] + g_pagg[n * 3 + 0] * inv;
            posOut[n * 3 + 1] = posIn[n * 3 + 1] + g_pagg[n * 3 + 1] * inv;
            posOut[n * 3 + 2] = posIn[n * 3 + 2] + g_pagg[n * 3 + 2] * inv;
            g_pagg[n * 3 + 0] = 0.f;
            g_pagg[n * 3 + 1] = 0.f;
            g_pagg[n * 3 + 2] = 0.f;
        }
    }
    __syncwarp();

    float acc[2][8][4];
#pragma unroll
    for (int mt = 0; mt < 2; ++mt)
#pragma unroll
        for (int nt = 0; nt < 8; ++nt)
#pragma unroll
            for (int i = 0; i < 4; ++i) acc[mt][nt][i] = 0.0f;

#pragma unroll
    for (int kt = 0; kt < 4; ++kt) stepK(acc, A_F, N1s, 36, 72, kt * 8, kt * 8, tb, g, cc);
#pragma unroll
    for (int kt = 0; kt < 4; ++kt) stepK(acc, A_M, N1s, 36, 72, kt * 8, 32 + kt * 8, tb, g, cc);

    // epilogue 1: silu -> packed A-fragments in registers
    u32 au[2][8], av[2][8];
#pragma unroll
    for (int mt = 0; mt < 2; ++mt) {
#pragma unroll
        for (int nt = 0; nt < 8; ++nt) {
            const int n0 = nt * 8 + 2 * cc;
            float v00 = silu_f(acc[mt][nt][0] + b1s[n0]);
            float v01 = silu_f(acc[mt][nt][1] + b1s[n0 + 1]);
            float v10 = silu_f(acc[mt][nt][2] + b1s[n0]);
            float v11 = silu_f(acc[mt][nt][3] + b1s[n0 + 1]);
            au[mt][nt] = pk2(v00, v01);
            av[mt][nt] = pk2(v10, v11);
        }
    }

    // stage 2: feat_out = h @ nW2 + nb2 (A from registers)
#pragma unroll
    for (int mt = 0; mt < 2; ++mt)
#pragma unroll
        for (int nt = 0; nt < 8; ++nt)
#pragma unroll
            for (int i = 0; i < 4; ++i) acc[mt][nt][i] = 0.0f;
#pragma unroll
    for (int kt = 0; kt < 4; ++kt) stepR(acc, au, av, N2s, 40, kt, g, cc);

#pragma unroll
    for (int mt = 0; mt < 2; ++mt) {
        const int m0 = tile * ETPB + tb + mt * 16 + g;
        const int m1 = m0 + 8;
#pragma unroll
        for (int nt = 0; nt < 8; ++nt) {
            const int n0 = nt * 8 + 2 * cc;
            const int word = nt * 4 + cc;
            if (m0 < NN)
                fout[(size_t)m0 * 32 + word] = pk2(acc[mt][nt][0] + b2s[n0], acc[mt][nt][1] + b2s[n0 + 1]);
            if (m1 < NN)
                fout[(size_t)m1 * 32 + word] = pk2(acc[mt][nt][2] + b2s[n0], acc[mt][nt][3] + b2s[n0 + 1]);
        }
    }
}

// ================= helper kernels =================
__global__ void init_kernel(const float* __restrict__ pos) {
    int i = blockIdx.x * blockDim.x + threadIdx.x;
    if (i < NN * 64) g_msg[i] = 0.0f;
    if (i < NN * 3) { g_pagg[i] = 0.0f; g_posB[i] = pos[i]; }
    if (i < NN) g_cnt[i] = 0;
}
__global__ void count_kernel(const int* __restrict__ row) {
    int e = blockIdx.x * blockDim.x + threadIdx.x;
    if (e < EE) atomicAdd(&g_cnt[row[e]], 1);
}
// k-permuted weight position: p = P&7; k = 16*(P>>3) + (p odd ? p+7 : p)
__global__ void prep_kernel(const float* __restrict__ nf, const float* __restrict__ embW,
                            const float* __restrict__ embb,
                            const float* __restrict__ mW1, const float* __restrict__ mW2,
                            const float* __restrict__ pW1,
                            const float* __restrict__ nW1, const float* __restrict__ nW2) {
    int i = blockIdx.x * blockDim.x + threadIdx.x;
    if (i < NN) g_inv[i] = 1.0f / fmaxf((float)g_cnt[i], 1.0f);
    if (i < NN * 32) {
        int n = i >> 5, w = i & 31;
        int J = 2 * w;
        float v0 = nf[2 * n] * embW[J] + nf[2 * n + 1] * embW[64 + J] + embb[J];
        float v1 = nf[2 * n] * embW[J + 1] + nf[2 * n + 1] * embW[64 + J + 1] + embb[J + 1];
        g_featPA[i] = pk2(v0, v1);
    }
    if (i < 5 * 8192) {
        int l = i >> 13, rem = i & 8191;
        u32 out;
        if (rem < 4096) {
            int n = rem >> 6, P = rem & 63;
            int p = P & 7;
            int k = 16 * (P >> 3) + ((p & 1) ? p + 7 : p);
            out = pk2(mW1[l * 131 * 64 + k * 64 + n], mW1[l * 131 * 64 + (k + 1) * 64 + n]);
        } else {
            int rem2 = rem - 4096;
            int mat = rem2 >> 11, idx = rem2 & 2047;
            int n = idx >> 5, P = idx & 31;
            int p = P & 7;
            int k = 16 * (P >> 3) + ((p & 1) ? p + 7 : p);
            const float* src = (mat == 0) ? mW2 : pW1;
            out = pk2(src[l * 4096 + k * 64 + n], src[l * 4096 + (k + 1) * 64 + n]);
        }
        g_wb[i] = out;
    }
    if (i < 5 * 6144) {
        int l = i / 6144, rem = i % 6144;
        u32 out;
        if (rem < 4096) {
            int n = rem >> 6, P = rem & 63;
            int p = P & 7;
            int k = 16 * (P >> 3) + ((p & 1) ? p + 7 : p);
            out = pk2(nW1[l * 8192 + k * 64 + n], nW1[l * 8192 + (k + 1) * 64 + n]);
        } else {
            int idx = rem - 4096;
            int n = idx >> 5, P = idx & 31;
            int p = P & 7;
            int k = 16 * (P >> 3) + ((p & 1) ? p + 7 : p);
            out = pk2(nW2[l * 4096 + k * 64 + n], nW2[l * 4096 + (k + 1) * 64 + n]);
        }
        g_wnb[i] = out;
    }
}
__global__ void pos_final_kernel(float* __restrict__ out) {
    int i = blockIdx.x * blockDim.x + threadIdx.x;
    if (i < NN * 3) {
        int n = i / 3;
        out[i] = g_posA[i] + g_pagg[i] * g_inv[n];
    }
}

extern "C" void kernel_launch(void* const* d_in, const int* in_sizes, int n_in,
                              void* d_out, int out_size)
{
    const float*  node_feat = (const float*)d_in[0];
    const float*  node_pos  = (const float*)d_in[1];
    const float2* edge_attr = (const float2*)d_in[2];
    const int*    row       = (const int*)d_in[3];
    const int*    col       = (const int*)d_in[4];
    const float*  emb_W     = (const float*)d_in[5];
    const float*  emb_b     = (const float*)d_in[6];
    const float*  mW1 = (const float*)d_in[7];
    const float*  mb1 = (const float*)d_in[8];
    const float*  mW2 = (const float*)d_in[9];
    const float*  mb2 = (const float*)d_in[10];
    const float*  pW1 = (const float*)d_in[11];
    const float*  pb1 = (const float*)d_in[12];
    const float*  pW2 = (const float*)d_in[13];
    const float*  pb2 = (const float*)d_in[14];
    const float*  nW1 = (const float*)d_in[15];
    const float*  nb1 = (const float*)d_in[16];
    const float*  nW2 = (const float*)d_in[17];
    const float*  nb2 = (const float*)d_in[18];
    float* out = (float*)d_out;

    cudaFuncSetAttribute(edge_kernel<true, false>, cudaFuncAttributeMaxDynamicSharedMemorySize, SM_TOT);
    cudaFuncSetAttribute(edge_kernel<true, true>,  cudaFuncAttributeMaxDynamicSharedMemorySize, SM_TOT);
    cudaFuncSetAttribute(edge_kernel<false, true>, cudaFuncAttributeMaxDynamicSharedMemorySize, SM_TOT);
    cudaFuncSetAttribute(node_mma_kernel<false>, cudaFuncAttributeMaxDynamicSharedMemorySize, NSM_TOT);
    cudaFuncSetAttribute(node_mma_kernel<true>,  cudaFuncAttributeMaxDynamicSharedMemorySize, NSM_TOT);

    const int ZG = (NN * 64 + 255) / 256;

    init_kernel<<<ZG, 256>>>(node_pos);
    count_kernel<<<(EE + 255) / 256, 256>>>(row);
    prep_kernel<<<ZG, 256>>>(node_feat, emb_W, emb_b, mW1, mW2, pW1, nW1, nW2);

#define EDGE_ARGS(l) edge_attr, row, col, \
        mW1 + (l) * 131 * 64, mb1 + (l) * 64, mb2 + (l) * 64, \
        pb1 + (l) * 64, pW2 + (l) * 64, pb2 + (l)

    // L0 (com_node_feat_net): feat only
    edge_kernel<true, false><<<EGRID, ETPB, SM_TOT>>>(0, 1, 0, EDGE_ARGS(0));
    node_mma_kernel<false><<<NTTILES, ETPB, NSM_TOT>>>(0, 1, 0, nb1 + 0, nb2 + 0);
    // L1
    edge_kernel<true, true><<<EGRID, ETPB, SM_TOT>>>(1, 1, 1, EDGE_ARGS(1));
    node_mma_kernel<true><<<NTTILES, ETPB, NSM_TOT>>>(1, 1, 1, nb1 + 64, nb2 + 64);
    // L2
    edge_kernel<true, true><<<EGRID, ETPB, SM_TOT>>>(0, 0, 2, EDGE_ARGS(2));
    node_mma_kernel<true><<<NTTILES, ETPB, NSM_TOT>>>(0, 0, 2, nb1 + 128, nb2 + 128);
    // L3
    edge_kernel<true, true><<<EGRID, ETPB, SM_TOT>>>(1, 1, 3, EDGE_ARGS(3));
    node_mma_kernel<true><<<NTTILES, ETPB, NSM_TOT>>>(1, 1, 3, nb1 + 192, nb2 + 192);
    // L4: pos only
    edge_kernel<false, true><<<EGRID, ETPB, SM_TOT>>>(0, 0, 4, EDGE_ARGS(4));
    pos_final_kernel<<<(NN * 3 + 255) / 256, 256>>>(out);

#undef EDGE_ARGS
}